// round 1
// baseline (speedup 1.0000x reference)
#include <cuda_runtime.h>
#include <cuda_bf16.h>
#include <cstddef>

// Shapes (fixed by the problem):
//   x    : (4, 2048, 256)  fp32
//   Wq   : (256, 1024)
//   Wk   : (256, 1024)
//   Wv   : (1024, 256)
//   gamma, beta : (256,)
// Outputs: out (4,2048,256), probs (4,4,2048,2048) — assumed concatenated in d_out.

#define BS   4
#define SEQ  2048
#define DIM  256
#define HH   4
#define HD   1024           // HH*DIM
#define BHN  16             // BS*HH

#define BM 128
#define BN 128
#define BK 8

// ---------------- scratch (device globals; allocation-free rule) ----------------
__device__ float g_Qp[(size_t)BHN * SEQ * DIM];     // 32 MB, (b,h,s,d) permuted Q
__device__ float g_Kp[(size_t)BHN * SEQ * DIM];     // 32 MB
__device__ float g_att[(size_t)BS * SEQ * HD];      // 32 MB, (b, s, h*d)
__device__ float g_Z[(size_t)BS * SEQ * DIM];       // 8 MB, pre-LN
__device__ float g_out_fb[(size_t)BS * SEQ * DIM];  // fallback out
__device__ float g_probs_fb[(size_t)BS * HH * SEQ * SEQ]; // 268 MB fallback probs

// =======================================================================
// Kernel 1: projection GEMM  C = X(8192x256) @ W(256x1024), permuted store
// =======================================================================
__global__ void k_proj(const float* __restrict__ X, const float* __restrict__ W,
                       float* __restrict__ outp)
{
    __shared__ float As[BK][BM];
    __shared__ float Bs[BK][BN];
    const int tid = threadIdx.x;
    const int tx = tid & 15, ty = tid >> 4;
    const int rowBase = blockIdx.y * BM;   // [0,8192)
    const int colBase = blockIdx.x * BN;   // [0,1024)
    const int arow = tid >> 1, acol = (tid & 1) * 4;
    const int brow = tid >> 5, bcol = (tid & 31) * 4;

    float acc[8][8];
#pragma unroll
    for (int m = 0; m < 8; ++m)
#pragma unroll
        for (int n = 0; n < 8; ++n) acc[m][n] = 0.f;

    for (int k0 = 0; k0 < 256; k0 += BK) {
        float4 av = *reinterpret_cast<const float4*>(&X[(size_t)(rowBase + arow) * 256 + k0 + acol]);
        As[acol + 0][arow] = av.x; As[acol + 1][arow] = av.y;
        As[acol + 2][arow] = av.z; As[acol + 3][arow] = av.w;
        float4 bv = *reinterpret_cast<const float4*>(&W[(size_t)(k0 + brow) * 1024 + colBase + bcol]);
        *reinterpret_cast<float4*>(&Bs[brow][bcol]) = bv;
        __syncthreads();
#pragma unroll
        for (int kk = 0; kk < BK; ++kk) {
            float a[8], b[8];
#pragma unroll
            for (int m = 0; m < 8; ++m) a[m] = As[kk][ty * 8 + m];
#pragma unroll
            for (int n = 0; n < 8; ++n) b[n] = Bs[kk][tx * 8 + n];
#pragma unroll
            for (int m = 0; m < 8; ++m)
#pragma unroll
                for (int n = 0; n < 8; ++n) acc[m][n] += a[m] * b[n];
        }
        __syncthreads();
    }

    // permuted store: (R=b*2048+r, c) -> (b, hh=r>>9, i=(r&511)*4+(c>>8), dd=c&255)
#pragma unroll
    for (int m = 0; m < 8; ++m) {
        int R = rowBase + ty * 8 + m;
        int b = R >> 11, r = R & 2047;
        int hh = r >> 9;
        int ibase = (r & 511) << 2;
#pragma unroll
        for (int n = 0; n < 8; ++n) {
            int c = colBase + tx * 8 + n;
            int i = ibase | (c >> 8);
            int dd = c & 255;
            outp[(((size_t)(b * 4 + hh)) * SEQ + i) * DIM + dd] = acc[m][n];
        }
    }
}

// =======================================================================
// Kernel 2: scores = (Qp @ Kp^T) / 16 per (b,h).  M=N=2048, K=256 (NT)
// =======================================================================
__global__ void k_scores(const float* __restrict__ Qp, const float* __restrict__ Kp,
                         float* __restrict__ probs)
{
    __shared__ float As[BK][BM];
    __shared__ float Bs[BK][BN];
    const int tid = threadIdx.x;
    const int tx = tid & 15, ty = tid >> 4;
    const int bh = blockIdx.z;
    const float* A = Qp + (size_t)bh * SEQ * DIM;
    const float* B = Kp + (size_t)bh * SEQ * DIM;
    const int iBase = blockIdx.y * BM;
    const int jBase = blockIdx.x * BN;
    const int lrow = tid >> 1, lcol = (tid & 1) * 4;

    float acc[8][8];
#pragma unroll
    for (int m = 0; m < 8; ++m)
#pragma unroll
        for (int n = 0; n < 8; ++n) acc[m][n] = 0.f;

    for (int k0 = 0; k0 < 256; k0 += BK) {
        float4 av = *reinterpret_cast<const float4*>(&A[(size_t)(iBase + lrow) * 256 + k0 + lcol]);
        As[lcol + 0][lrow] = av.x; As[lcol + 1][lrow] = av.y;
        As[lcol + 2][lrow] = av.z; As[lcol + 3][lrow] = av.w;
        float4 bv = *reinterpret_cast<const float4*>(&B[(size_t)(jBase + lrow) * 256 + k0 + lcol]);
        Bs[lcol + 0][lrow] = bv.x; Bs[lcol + 1][lrow] = bv.y;
        Bs[lcol + 2][lrow] = bv.z; Bs[lcol + 3][lrow] = bv.w;
        __syncthreads();
#pragma unroll
        for (int kk = 0; kk < BK; ++kk) {
            float a[8], b[8];
#pragma unroll
            for (int m = 0; m < 8; ++m) a[m] = As[kk][ty * 8 + m];
#pragma unroll
            for (int n = 0; n < 8; ++n) b[n] = Bs[kk][tx * 8 + n];
#pragma unroll
            for (int m = 0; m < 8; ++m)
#pragma unroll
                for (int n = 0; n < 8; ++n) acc[m][n] += a[m] * b[n];
        }
        __syncthreads();
    }

    float* outp = probs + (size_t)bh * SEQ * SEQ;
#pragma unroll
    for (int m = 0; m < 8; ++m) {
        int gi = iBase + ty * 8 + m;
#pragma unroll
        for (int n = 0; n < 8; ++n) {
            int gj = jBase + tx * 8 + n;
            outp[(size_t)gi * SEQ + gj] = acc[m][n] * 0.0625f;
        }
    }
}

// =======================================================================
// Kernel 3: in-place row softmax over 2048 elements (one block / row)
// =======================================================================
__global__ void k_softmax(float* __restrict__ probs)
{
    const size_t row = blockIdx.x;
    float* p = probs + row * SEQ;
    const int t = threadIdx.x;     // 256 threads, 8 elems each (strided)
    __shared__ float red[256];

    float v[8];
    float mx = -1e30f;
#pragma unroll
    for (int q = 0; q < 8; ++q) { v[q] = p[t + 256 * q]; mx = fmaxf(mx, v[q]); }
    red[t] = mx; __syncthreads();
    for (int s = 128; s > 0; s >>= 1) {
        if (t < s) red[t] = fmaxf(red[t], red[t + s]);
        __syncthreads();
    }
    mx = red[0]; __syncthreads();

    float sum = 0.f;
#pragma unroll
    for (int q = 0; q < 8; ++q) { v[q] = expf(v[q] - mx); sum += v[q]; }
    red[t] = sum; __syncthreads();
    for (int s = 128; s > 0; s >>= 1) {
        if (t < s) red[t] += red[t + s];
        __syncthreads();
    }
    float inv = 1.0f / red[0];
#pragma unroll
    for (int q = 0; q < 8; ++q) p[t + 256 * q] = v[q] * inv;
}

// =======================================================================
// Kernel 4: att_out = probs @ x[b] per (b,h).  M=2048, N=256, K=2048 (NN)
//           stored as (b, i, h*256 + dd)
// =======================================================================
__global__ void k_pv(const float* __restrict__ probs, const float* __restrict__ x,
                     float* __restrict__ att)
{
    __shared__ float As[BK][BM];
    __shared__ float Bs[BK][BN];
    const int tid = threadIdx.x;
    const int tx = tid & 15, ty = tid >> 4;
    const int bh = blockIdx.z;
    const int b = bh >> 2, h = bh & 3;
    const float* A = probs + (size_t)bh * SEQ * SEQ;   // lda 2048
    const float* B = x + (size_t)b * SEQ * DIM;        // ldb 256
    const int iBase = blockIdx.y * BM;
    const int cBase = blockIdx.x * BN;                 // {0, 128}
    const int arow = tid >> 1, acol = (tid & 1) * 4;
    const int brow = tid >> 5, bcol = (tid & 31) * 4;

    float acc[8][8];
#pragma unroll
    for (int m = 0; m < 8; ++m)
#pragma unroll
        for (int n = 0; n < 8; ++n) acc[m][n] = 0.f;

    for (int k0 = 0; k0 < SEQ; k0 += BK) {
        float4 av = *reinterpret_cast<const float4*>(&A[(size_t)(iBase + arow) * SEQ + k0 + acol]);
        As[acol + 0][arow] = av.x; As[acol + 1][arow] = av.y;
        As[acol + 2][arow] = av.z; As[acol + 3][arow] = av.w;
        float4 bv = *reinterpret_cast<const float4*>(&B[(size_t)(k0 + brow) * 256 + cBase + bcol]);
        *reinterpret_cast<float4*>(&Bs[brow][bcol]) = bv;
        __syncthreads();
#pragma unroll
        for (int kk = 0; kk < BK; ++kk) {
            float a[8], bb[8];
#pragma unroll
            for (int m = 0; m < 8; ++m) a[m] = As[kk][ty * 8 + m];
#pragma unroll
            for (int n = 0; n < 8; ++n) bb[n] = Bs[kk][tx * 8 + n];
#pragma unroll
            for (int m = 0; m < 8; ++m)
#pragma unroll
                for (int n = 0; n < 8; ++n) acc[m][n] += a[m] * bb[n];
        }
        __syncthreads();
    }

#pragma unroll
    for (int m = 0; m < 8; ++m) {
        int gi = iBase + ty * 8 + m;
#pragma unroll
        for (int n = 0; n < 8; ++n) {
            int gc = cBase + tx * 8 + n;     // [0,256)
            att[((size_t)b * SEQ + gi) * HD + h * 256 + gc] = acc[m][n];
        }
    }
}

// =======================================================================
// Kernel 5: Z = att(8192x1024) @ Wv(1024x256) + x  (NN)
// =======================================================================
__global__ void k_wv(const float* __restrict__ att, const float* __restrict__ Wv,
                     const float* __restrict__ x, float* __restrict__ Z)
{
    __shared__ float As[BK][BM];
    __shared__ float Bs[BK][BN];
    const int tid = threadIdx.x;
    const int tx = tid & 15, ty = tid >> 4;
    const int rowBase = blockIdx.y * BM;   // [0,8192)
    const int cBase = blockIdx.x * BN;     // {0,128}
    const int arow = tid >> 1, acol = (tid & 1) * 4;
    const int brow = tid >> 5, bcol = (tid & 31) * 4;

    float acc[8][8];
#pragma unroll
    for (int m = 0; m < 8; ++m)
#pragma unroll
        for (int n = 0; n < 8; ++n) acc[m][n] = 0.f;

    for (int k0 = 0; k0 < HD; k0 += BK) {
        float4 av = *reinterpret_cast<const float4*>(&att[(size_t)(rowBase + arow) * HD + k0 + acol]);
        As[acol + 0][arow] = av.x; As[acol + 1][arow] = av.y;
        As[acol + 2][arow] = av.z; As[acol + 3][arow] = av.w;
        float4 bv = *reinterpret_cast<const float4*>(&Wv[(size_t)(k0 + brow) * 256 + cBase + bcol]);
        *reinterpret_cast<float4*>(&Bs[brow][bcol]) = bv;
        __syncthreads();
#pragma unroll
        for (int kk = 0; kk < BK; ++kk) {
            float a[8], b[8];
#pragma unroll
            for (int m = 0; m < 8; ++m) a[m] = As[kk][ty * 8 + m];
#pragma unroll
            for (int n = 0; n < 8; ++n) b[n] = Bs[kk][tx * 8 + n];
#pragma unroll
            for (int m = 0; m < 8; ++m)
#pragma unroll
                for (int n = 0; n < 8; ++n) acc[m][n] += a[m] * b[n];
        }
        __syncthreads();
    }

#pragma unroll
    for (int m = 0; m < 8; ++m) {
        int R = rowBase + ty * 8 + m;
#pragma unroll
        for (int n = 0; n < 8; ++n) {
            int c = cBase + tx * 8 + n;
            size_t off = (size_t)R * 256 + c;
            Z[off] = acc[m][n] + x[off];
        }
    }
}

// =======================================================================
// Kernel 6: LayerNorm over last dim (256) — one block per row
// =======================================================================
__global__ void k_ln(const float* __restrict__ Z, const float* __restrict__ gamma,
                     const float* __restrict__ beta, float* __restrict__ outp)
{
    const int R = blockIdx.x;
    const int t = threadIdx.x;   // 256
    __shared__ float red[256];

    float z = Z[(size_t)R * 256 + t];
    red[t] = z; __syncthreads();
    for (int s = 128; s > 0; s >>= 1) {
        if (t < s) red[t] += red[t + s];
        __syncthreads();
    }
    float mu = red[0] * (1.0f / 256.0f);
    __syncthreads();

    float dev = z - mu;
    red[t] = dev * dev; __syncthreads();
    for (int s = 128; s > 0; s >>= 1) {
        if (t < s) red[t] += red[t + s];
        __syncthreads();
    }
    float var = red[0] * (1.0f / 256.0f);
    outp[(size_t)R * 256 + t] = dev * rsqrtf(var + 1e-5f) * gamma[t] + beta[t];
}

// =======================================================================
// Launch
// =======================================================================
extern "C" void kernel_launch(void* const* d_in, const int* in_sizes, int n_in,
                              void* d_out, int out_size)
{
    const float* x     = (const float*)d_in[0];
    const float* Wq    = (const float*)d_in[1];
    const float* Wk    = (const float*)d_in[2];
    const float* Wv    = (const float*)d_in[3];
    const float* gamma = (const float*)d_in[4];
    const float* beta  = (const float*)d_in[5];

    float *pQ, *pK, *pAtt, *pZ, *pOutFb, *pProbsFb;
    cudaGetSymbolAddress((void**)&pQ, g_Qp);
    cudaGetSymbolAddress((void**)&pK, g_Kp);
    cudaGetSymbolAddress((void**)&pAtt, g_att);
    cudaGetSymbolAddress((void**)&pZ, g_Z);
    cudaGetSymbolAddress((void**)&pOutFb, g_out_fb);
    cudaGetSymbolAddress((void**)&pProbsFb, g_probs_fb);

    const long long OUT_E = (long long)BS * SEQ * DIM;          // 2,097,152
    const long long PR_E  = (long long)BS * HH * SEQ * SEQ;     // 67,108,864
    long long osz = out_size;

    float* outp;
    float* probs;
    if (osz >= OUT_E + PR_E)      { outp = (float*)d_out; probs = (float*)d_out + OUT_E; }
    else if (osz >= PR_E)         { probs = (float*)d_out; outp = pOutFb; }
    else                          { outp = (float*)d_out; probs = pProbsFb; }

    dim3 T(256);
    k_proj   <<<dim3(8, 64),      T>>>(x, Wq, pQ);
    k_proj   <<<dim3(8, 64),      T>>>(x, Wk, pK);
    k_scores <<<dim3(16, 16, 16), T>>>(pQ, pK, probs);
    k_softmax<<<BHN * SEQ,        T>>>(probs);
    k_pv     <<<dim3(2, 16, 16),  T>>>(probs, x, pAtt);
    k_wv     <<<dim3(2, 64),      T>>>(pAtt, Wv, x, pZ);
    k_ln     <<<BS * SEQ,         T>>>(pZ, gamma, beta, outp);
}

// round 3
// speedup vs baseline: 2.8034x; 2.8034x over previous
#include <cuda_runtime.h>
#include <cuda_bf16.h>
#include <cstdint>
#include <cstddef>

#define BS   4
#define SEQ  2048
#define DIM  256
#define HH   4
#define HD   1024
#define BHN  16

typedef __nv_bfloat16 bf16;

// ======================= device scratch (no allocs allowed) =======================
__device__ __align__(256) bf16 g_xh  [(size_t)BS*SEQ*DIM];
__device__ __align__(256) bf16 g_xl  [(size_t)BS*SEQ*DIM];
__device__ __align__(256) bf16 g_xTh [(size_t)BS*DIM*SEQ];
__device__ __align__(256) bf16 g_xTl [(size_t)BS*DIM*SEQ];
__device__ __align__(256) bf16 g_wqth[(size_t)HD*DIM];
__device__ __align__(256) bf16 g_wqtl[(size_t)HD*DIM];
__device__ __align__(256) bf16 g_wkth[(size_t)HD*DIM];
__device__ __align__(256) bf16 g_wktl[(size_t)HD*DIM];
__device__ __align__(256) bf16 g_wvth[(size_t)DIM*HD];
__device__ __align__(256) bf16 g_wvtl[(size_t)DIM*HD];
__device__ __align__(256) bf16 g_Qh  [(size_t)BHN*SEQ*DIM];
__device__ __align__(256) bf16 g_Ql  [(size_t)BHN*SEQ*DIM];
__device__ __align__(256) bf16 g_Kh  [(size_t)BHN*SEQ*DIM];
__device__ __align__(256) bf16 g_Kl  [(size_t)BHN*SEQ*DIM];
__device__ __align__(256) bf16 g_Ph  [(size_t)BHN*SEQ*SEQ];
__device__ __align__(256) bf16 g_Pl  [(size_t)BHN*SEQ*SEQ];
__device__ __align__(256) bf16 g_atth[(size_t)BS*SEQ*HD];
__device__ __align__(256) bf16 g_attl[(size_t)BS*SEQ*HD];
__device__ __align__(256) float g_Z   [(size_t)BS*SEQ*DIM];
__device__ __align__(256) float g_out_fb [(size_t)BS*SEQ*DIM];
__device__ __align__(256) float g_probs_fb[(size_t)BHN*SEQ*SEQ];

// ======================= helpers =======================
__device__ __forceinline__ uint32_t smem_u32(const void* p) {
    uint32_t a;
    asm("{ .reg .u64 t; cvta.to.shared.u64 t, %1; cvt.u32.u64 %0, t; }" : "=r"(a) : "l"(p));
    return a;
}
#define CP16(dst, src) \
    asm volatile("cp.async.cg.shared.global [%0], [%1], 16;" :: "r"(dst), "l"(src))
#define CP_COMMIT() asm volatile("cp.async.commit_group;" ::: "memory")
#define CP_WAIT0()  asm volatile("cp.async.wait_group 0;" ::: "memory")
#define CP_WAIT1()  asm volatile("cp.async.wait_group 1;" ::: "memory")

#define LDSM4(r0, r1, r2, r3, a) \
    asm volatile("ldmatrix.sync.aligned.m8n8.x4.shared.b16 {%0,%1,%2,%3}, [%4];" \
        : "=r"(r0), "=r"(r1), "=r"(r2), "=r"(r3) : "r"(a))

#define MMA16816(d, a, b) \
    asm volatile("mma.sync.aligned.m16n8k16.row.col.f32.bf16.bf16.f32 " \
        "{%0,%1,%2,%3}, {%4,%5,%6,%7}, {%8,%9}, {%0,%1,%2,%3};" \
        : "+f"((d)[0]), "+f"((d)[1]), "+f"((d)[2]), "+f"((d)[3]) \
        : "r"((a)[0]), "r"((a)[1]), "r"((a)[2]), "r"((a)[3]), \
          "r"((b)[0]), "r"((b)[1]))

__device__ __forceinline__ void split2(float v, bf16& h, bf16& l) {
    h = __float2bfloat16_rn(v);
    l = __float2bfloat16_rn(v - __bfloat162float(h));
}

// ======================= prep kernels =======================
__global__ void k_split(const float* __restrict__ in, bf16* __restrict__ oh,
                        bf16* __restrict__ ol, int n)
{
    int i = blockIdx.x * 256 + threadIdx.x;
    if (i < n) { bf16 h, l; split2(in[i], h, l); oh[i] = h; ol[i] = l; }
}

__global__ void k_tsplit(const float* __restrict__ in, bf16* __restrict__ oh,
                         bf16* __restrict__ ol, int R, int C,
                         size_t inz, size_t outz)
{
    in += (size_t)blockIdx.z * inz;
    oh += (size_t)blockIdx.z * outz;
    ol += (size_t)blockIdx.z * outz;
    __shared__ float t[32][33];
    int c0 = blockIdx.x * 32, r0 = blockIdx.y * 32;
    int tx = threadIdx.x, ty = threadIdx.y;   // (32, 8)
#pragma unroll
    for (int i = 0; i < 4; ++i)
        t[ty + i * 8][tx] = in[(size_t)(r0 + ty + i * 8) * C + c0 + tx];
    __syncthreads();
#pragma unroll
    for (int i = 0; i < 4; ++i) {
        float v = t[tx][ty + i * 8];
        bf16 h, l; split2(v, h, l);
        size_t o = (size_t)(c0 + ty + i * 8) * R + r0 + tx;
        oh[o] = h; ol[o] = l;
    }
}

// ======================= warp-MMA GEMM (bf16 3-product split) =======================
// MODE 0: proj  -> permuted bf16-split store (Q or K)
// MODE 1: scores-> fp32 * 1/16 to probs
// MODE 2: pv    -> bf16-split store to att (b, i, h*256+c)
// MODE 3: wv    -> fp32 + residual to Z
#define SMEM_BYTES (2 * 4 * 16384)   // 2 stages x (Ah,Al,Bh,Bl) x 16KB

template<int MODE>
__global__ void __launch_bounds__(256, 1)
k_mma(const bf16* __restrict__ Ah, const bf16* __restrict__ Al,
      const bf16* __restrict__ Bh, const bf16* __restrict__ Bl,
      int lda, int ldb, int K,
      size_t strideAz, size_t strideBz, int bShift,
      float* __restrict__ ep_f, bf16* __restrict__ ep_h, bf16* __restrict__ ep_l,
      const float* __restrict__ resid, size_t strideEz)
{
    extern __shared__ __align__(1024) char smem[];
    const int tid = threadIdx.x;
    const int wid = tid >> 5, lane = tid & 31;
    const int wm = wid >> 2, wn = wid & 3;          // 2 x 4 warp grid
    const int mBase = blockIdx.y * 128, nBase = blockIdx.x * 128;
    const int z = blockIdx.z;

    const bf16* A0 = Ah + (size_t)z * strideAz;
    const bf16* A1 = Al + (size_t)z * strideAz;
    const bf16* B0 = Bh + (size_t)(z >> bShift) * strideBz;
    const bf16* B1 = Bl + (size_t)(z >> bShift) * strideBz;

    const int nch = K >> 6;   // Kc = 64

    // ldmatrix per-lane geometry (identical formula for A and B tiles)
    const int lrow = (lane & 7) + ((lane >> 3) & 1) * 8;
    const int kh16 = ((lane >> 4) & 1) * 16;
    const int swz  = (lane & 7) << 4;
    int rA[4], rB[2];
#pragma unroll
    for (int bm = 0; bm < 4; ++bm) rA[bm] = (wm * 64 + bm * 16 + lrow) * 128;
#pragma unroll
    for (int nb = 0; nb < 2; ++nb) rB[nb] = (wn * 32 + nb * 16 + lrow) * 128;

    float acc[4][4][4];
#pragma unroll
    for (int a = 0; a < 4; ++a)
#pragma unroll
        for (int b = 0; b < 4; ++b)
#pragma unroll
            for (int c = 0; c < 4; ++c) acc[a][b][c] = 0.f;

    // ---- cp.async chunk loader: 4 tiles of 128x64 bf16, SW128-swizzled ----
#define LOAD_CHUNK(chunk, buf)                                                     \
    {                                                                              \
        const int k0_ = (chunk) * 64;                                              \
        const bf16* srcs_[4] = {A0, A1, B0, B1};                                   \
        _Pragma("unroll")                                                          \
        for (int t_ = 0; t_ < 4; ++t_) {                                           \
            const bf16* s_ = srcs_[t_];                                            \
            const int ld_ = (t_ < 2) ? lda : ldb;                                  \
            const int rb_ = (t_ < 2) ? mBase : nBase;                              \
            const uint32_t sb_ = smem_u32(smem) + (buf) * 65536 + t_ * 16384;      \
            _Pragma("unroll")                                                      \
            for (int j_ = 0; j_ < 4; ++j_) {                                       \
                int idx_ = tid + 256 * j_;                                         \
                int row_ = idx_ >> 3, c16_ = idx_ & 7;                             \
                const bf16* g_ = s_ + (size_t)(rb_ + row_) * ld_ + k0_ + c16_ * 8; \
                uint32_t d_ = sb_ + row_ * 128 + ((c16_ * 16) ^ ((row_ & 7) << 4));\
                CP16(d_, g_);                                                      \
            }                                                                      \
        }                                                                          \
    }

    LOAD_CHUNK(0, 0);
    CP_COMMIT();

    for (int i = 0; i < nch; ++i) {
        if (i + 1 < nch) { LOAD_CHUNK(i + 1, (i + 1) & 1); CP_COMMIT(); CP_WAIT1(); }
        else             { CP_WAIT0(); }
        __syncthreads();

        const uint32_t tb = smem_u32(smem) + (i & 1) * 65536;
        const uint32_t sAh = tb, sAl = tb + 16384, sBh = tb + 32768, sBl = tb + 49152;
#pragma unroll
        for (int ks = 0; ks < 4; ++ks) {
            const int cz = ((ks * 32) + kh16) ^ swz;
            uint32_t ah[4][4], al[4][4];
#pragma unroll
            for (int bm = 0; bm < 4; ++bm) {
                LDSM4(ah[bm][0], ah[bm][1], ah[bm][2], ah[bm][3], sAh + rA[bm] + cz);
                LDSM4(al[bm][0], al[bm][1], al[bm][2], al[bm][3], sAl + rA[bm] + cz);
            }
            uint32_t bh[4][2], bl[4][2];
#pragma unroll
            for (int nb = 0; nb < 2; ++nb) {
                uint32_t t0, t1, t2, t3;
                LDSM4(t0, t1, t2, t3, sBh + rB[nb] + cz);
                bh[nb * 2][0] = t0; bh[nb * 2][1] = t2;
                bh[nb * 2 + 1][0] = t1; bh[nb * 2 + 1][1] = t3;
                LDSM4(t0, t1, t2, t3, sBl + rB[nb] + cz);
                bl[nb * 2][0] = t0; bl[nb * 2][1] = t2;
                bl[nb * 2 + 1][0] = t1; bl[nb * 2 + 1][1] = t3;
            }
#pragma unroll
            for (int bm = 0; bm < 4; ++bm)
#pragma unroll
                for (int bn = 0; bn < 4; ++bn) MMA16816(acc[bm][bn], ah[bm], bh[bn]);
#pragma unroll
            for (int bm = 0; bm < 4; ++bm)
#pragma unroll
                for (int bn = 0; bn < 4; ++bn) MMA16816(acc[bm][bn], ah[bm], bl[bn]);
#pragma unroll
            for (int bm = 0; bm < 4; ++bm)
#pragma unroll
                for (int bn = 0; bn < 4; ++bn) MMA16816(acc[bm][bn], al[bm], bh[bn]);
        }
        __syncthreads();
    }
#undef LOAD_CHUNK

    // ======================= epilogue =======================
    const int g4 = lane >> 2, t4 = lane & 3;
#pragma unroll
    for (int bm = 0; bm < 4; ++bm) {
#pragma unroll
        for (int bn = 0; bn < 4; ++bn) {
            const int r0 = mBase + wm * 64 + bm * 16 + g4;
            const int c0 = nBase + wn * 32 + bn * 8 + t4 * 2;
            const float* a4 = acc[bm][bn];
#pragma unroll
            for (int half = 0; half < 2; ++half) {
                const int gr = r0 + half * 8;
                const float v0 = a4[half * 2 + 0];
                const float v1 = a4[half * 2 + 1];
                if (MODE == 1) {
                    float2 q; q.x = v0 * 0.0625f; q.y = v1 * 0.0625f;
                    *reinterpret_cast<float2*>(
                        ep_f + (size_t)z * strideEz + (size_t)gr * SEQ + c0) = q;
                } else if (MODE == 3) {
                    size_t off = (size_t)gr * DIM + c0;
                    float2 rx = *reinterpret_cast<const float2*>(resid + off);
                    float2 q; q.x = v0 + rx.x; q.y = v1 + rx.y;
                    *reinterpret_cast<float2*>(ep_f + off) = q;
                } else if (MODE == 0) {
                    const int bb = gr >> 11, rr = gr & 2047;
                    const int hh = rr >> 9, ib = (rr & 511) << 2;
                    const int ii = ib | (c0 >> 8), dd = c0 & 255;
                    size_t base = ((size_t)(bb * 4 + hh) * SEQ + ii) * DIM + dd;
                    bf16 h0, l0, h1, l1;
                    split2(v0, h0, l0); split2(v1, h1, l1);
                    __nv_bfloat162 ph; ph.x = h0; ph.y = h1;
                    __nv_bfloat162 pl; pl.x = l0; pl.y = l1;
                    *reinterpret_cast<__nv_bfloat162*>(ep_h + base) = ph;
                    *reinterpret_cast<__nv_bfloat162*>(ep_l + base) = pl;
                } else {  // MODE 2
                    const int bb = z >> 2, h = z & 3;
                    size_t base = ((size_t)(bb * SEQ + gr)) * HD + h * DIM + c0;
                    bf16 h0, l0, h1, l1;
                    split2(v0, h0, l0); split2(v1, h1, l1);
                    __nv_bfloat162 ph; ph.x = h0; ph.y = h1;
                    __nv_bfloat162 pl; pl.x = l0; pl.y = l1;
                    *reinterpret_cast<__nv_bfloat162*>(ep_h + base) = ph;
                    *reinterpret_cast<__nv_bfloat162*>(ep_l + base) = pl;
                }
            }
        }
    }
}

// ======================= softmax (in-place) + bf16 split out =======================
__global__ void k_softmax(float* __restrict__ probs, bf16* __restrict__ ph,
                          bf16* __restrict__ pl)
{
    const size_t row = blockIdx.x;
    float* p = probs + row * SEQ;
    const int t = threadIdx.x;
    __shared__ float red[256];

    float v[8];
    float mx = -1e30f;
#pragma unroll
    for (int q = 0; q < 8; ++q) { v[q] = p[t + 256 * q]; mx = fmaxf(mx, v[q]); }
    red[t] = mx; __syncthreads();
    for (int s = 128; s > 0; s >>= 1) {
        if (t < s) red[t] = fmaxf(red[t], red[t + s]);
        __syncthreads();
    }
    mx = red[0]; __syncthreads();

    float sum = 0.f;
#pragma unroll
    for (int q = 0; q < 8; ++q) { v[q] = expf(v[q] - mx); sum += v[q]; }
    red[t] = sum; __syncthreads();
    for (int s = 128; s > 0; s >>= 1) {
        if (t < s) red[t] += red[t + s];
        __syncthreads();
    }
    const float inv = 1.0f / red[0];
    const size_t ro = row * SEQ;
#pragma unroll
    for (int q = 0; q < 8; ++q) {
        float val = v[q] * inv;
        int idx = t + 256 * q;
        p[idx] = val;
        bf16 h, l; split2(val, h, l);
        ph[ro + idx] = h; pl[ro + idx] = l;
    }
}

// ======================= LayerNorm =======================
__global__ void k_ln(const float* __restrict__ Z, const float* __restrict__ gamma,
                     const float* __restrict__ beta, float* __restrict__ outp)
{
    const int R = blockIdx.x;
    const int t = threadIdx.x;
    __shared__ float red[256];

    float zv = Z[(size_t)R * DIM + t];
    red[t] = zv; __syncthreads();
    for (int s = 128; s > 0; s >>= 1) {
        if (t < s) red[t] += red[t + s];
        __syncthreads();
    }
    float mu = red[0] * (1.0f / 256.0f);
    __syncthreads();
    float dev = zv - mu;
    red[t] = dev * dev; __syncthreads();
    for (int s = 128; s > 0; s >>= 1) {
        if (t < s) red[t] += red[t + s];
        __syncthreads();
    }
    float var = red[0] * (1.0f / 256.0f);
    outp[(size_t)R * DIM + t] = dev * rsqrtf(var + 1e-5f) * gamma[t] + beta[t];
}

// ======================= launch =======================
extern "C" void kernel_launch(void* const* d_in, const int* in_sizes, int n_in,
                              void* d_out, int out_size)
{
    const float* x     = (const float*)d_in[0];
    const float* Wq    = (const float*)d_in[1];
    const float* Wk    = (const float*)d_in[2];
    const float* Wv    = (const float*)d_in[3];
    const float* gamma = (const float*)d_in[4];
    const float* beta  = (const float*)d_in[5];

    bf16 *xh, *xl, *xTh, *xTl, *wqth, *wqtl, *wkth, *wktl, *wvth, *wvtl;
    bf16 *Qh, *Ql, *Kh, *Kl, *Ph, *Pl, *atth, *attl;
    float *Z, *outFb, *probsFb;
    cudaGetSymbolAddress((void**)&xh, g_xh);     cudaGetSymbolAddress((void**)&xl, g_xl);
    cudaGetSymbolAddress((void**)&xTh, g_xTh);   cudaGetSymbolAddress((void**)&xTl, g_xTl);
    cudaGetSymbolAddress((void**)&wqth, g_wqth); cudaGetSymbolAddress((void**)&wqtl, g_wqtl);
    cudaGetSymbolAddress((void**)&wkth, g_wkth); cudaGetSymbolAddress((void**)&wktl, g_wktl);
    cudaGetSymbolAddress((void**)&wvth, g_wvth); cudaGetSymbolAddress((void**)&wvtl, g_wvtl);
    cudaGetSymbolAddress((void**)&Qh, g_Qh);     cudaGetSymbolAddress((void**)&Ql, g_Ql);
    cudaGetSymbolAddress((void**)&Kh, g_Kh);     cudaGetSymbolAddress((void**)&Kl, g_Kl);
    cudaGetSymbolAddress((void**)&Ph, g_Ph);     cudaGetSymbolAddress((void**)&Pl, g_Pl);
    cudaGetSymbolAddress((void**)&atth, g_atth); cudaGetSymbolAddress((void**)&attl, g_attl);
    cudaGetSymbolAddress((void**)&Z, g_Z);
    cudaGetSymbolAddress((void**)&outFb, g_out_fb);
    cudaGetSymbolAddress((void**)&probsFb, g_probs_fb);

    const long long OUT_E = (long long)BS * SEQ * DIM;
    const long long PR_E  = (long long)BHN * SEQ * SEQ;
    long long osz = out_size;
    float *outp, *probs;
    if (osz >= OUT_E + PR_E) { outp = (float*)d_out; probs = (float*)d_out + OUT_E; }
    else if (osz >= PR_E)    { probs = (float*)d_out; outp = outFb; }
    else                     { outp = (float*)d_out; probs = probsFb; }

    cudaFuncSetAttribute(k_mma<0>, cudaFuncAttributeMaxDynamicSharedMemorySize, SMEM_BYTES);
    cudaFuncSetAttribute(k_mma<1>, cudaFuncAttributeMaxDynamicSharedMemorySize, SMEM_BYTES);
    cudaFuncSetAttribute(k_mma<2>, cudaFuncAttributeMaxDynamicSharedMemorySize, SMEM_BYTES);
    cudaFuncSetAttribute(k_mma<3>, cudaFuncAttributeMaxDynamicSharedMemorySize, SMEM_BYTES);

    dim3 T(256);
    const int NX = BS * SEQ * DIM;

    // --- prep: splits & transposes ---
    k_split <<<NX / 256, T>>>(x, xh, xl, NX);
    k_tsplit<<<dim3(32, 8, 1),  dim3(32, 8)>>>(Wq, wqth, wqtl, 256, 1024, 0, 0);
    k_tsplit<<<dim3(32, 8, 1),  dim3(32, 8)>>>(Wk, wkth, wktl, 256, 1024, 0, 0);
    k_tsplit<<<dim3(8, 32, 1),  dim3(32, 8)>>>(Wv, wvth, wvtl, 1024, 256, 0, 0);
    k_tsplit<<<dim3(8, 64, 4),  dim3(32, 8)>>>(x, xTh, xTl, 2048, 256,
                                               (size_t)SEQ * DIM, (size_t)SEQ * DIM);

    // --- Q, K projections (M=8192, N=1024, K=256), permuted bf16-split epilogue ---
    k_mma<0><<<dim3(8, 64, 1), T, SMEM_BYTES>>>(xh, xl, wqth, wqtl, 256, 256, 256,
        0, 0, 0, nullptr, Qh, Ql, nullptr, 0);
    k_mma<0><<<dim3(8, 64, 1), T, SMEM_BYTES>>>(xh, xl, wkth, wktl, 256, 256, 256,
        0, 0, 0, nullptr, Kh, Kl, nullptr, 0);

    // --- scores (per bh: 2048x2048, K=256), scaled fp32 epilogue ---
    k_mma<1><<<dim3(16, 16, BHN), T, SMEM_BYTES>>>(Qh, Ql, Kh, Kl, 256, 256, 256,
        (size_t)SEQ * DIM, (size_t)SEQ * DIM, 0, probs, nullptr, nullptr, nullptr,
        (size_t)SEQ * SEQ);

    // --- softmax + probs bf16 split ---
    k_softmax<<<BHN * SEQ, T>>>(probs, Ph, Pl);

    // --- PV (per bh: 2048x256, K=2048), bf16-split att epilogue ---
    k_mma<2><<<dim3(2, 16, BHN), T, SMEM_BYTES>>>(Ph, Pl, xTh, xTl, 2048, 2048, 2048,
        (size_t)SEQ * SEQ, (size_t)DIM * SEQ, 2, nullptr, atth, attl, nullptr, 0);

    // --- att @ Wv + x (M=8192, N=256, K=1024), fp32 residual epilogue ---
    k_mma<3><<<dim3(2, 64, 1), T, SMEM_BYTES>>>(atth, attl, wvth, wvtl, 1024, 1024, 1024,
        0, 0, 0, Z, nullptr, nullptr, x, 0);

    // --- LayerNorm ---
    k_ln<<<BS * SEQ, T>>>(Z, gamma, beta, outp);
}

// round 4
// speedup vs baseline: 2.8901x; 1.0309x over previous
#include <cuda_runtime.h>
#include <cuda_bf16.h>
#include <cstdint>
#include <cstddef>

#define BS   4
#define SEQ  2048
#define DIM  256
#define HH   4
#define HD   1024
#define BHN  16

typedef __nv_bfloat16 bf16;

// ======================= device scratch (no allocs allowed) =======================
__device__ __align__(256) bf16 g_xh  [(size_t)BS*SEQ*DIM];
__device__ __align__(256) bf16 g_xl  [(size_t)BS*SEQ*DIM];
__device__ __align__(256) bf16 g_xTh [(size_t)BS*DIM*SEQ];
__device__ __align__(256) bf16 g_xTl [(size_t)BS*DIM*SEQ];
__device__ __align__(256) bf16 g_wqth[(size_t)HD*DIM];
__device__ __align__(256) bf16 g_wqtl[(size_t)HD*DIM];
__device__ __align__(256) bf16 g_wkth[(size_t)HD*DIM];
__device__ __align__(256) bf16 g_wktl[(size_t)HD*DIM];
__device__ __align__(256) bf16 g_wvth[(size_t)DIM*HD];
__device__ __align__(256) bf16 g_wvtl[(size_t)DIM*HD];
__device__ __align__(256) bf16 g_Qh  [(size_t)BHN*SEQ*DIM];
__device__ __align__(256) bf16 g_Ql  [(size_t)BHN*SEQ*DIM];
__device__ __align__(256) bf16 g_Kh  [(size_t)BHN*SEQ*DIM];
__device__ __align__(256) bf16 g_Kl  [(size_t)BHN*SEQ*DIM];
__device__ __align__(256) bf16 g_atth[(size_t)BS*SEQ*HD];
__device__ __align__(256) bf16 g_attl[(size_t)BS*SEQ*HD];
__device__ __align__(256) float g_Z   [(size_t)BS*SEQ*DIM];
__device__ __align__(256) float g_out_fb [(size_t)BS*SEQ*DIM];
__device__ __align__(256) float g_probs_fb[(size_t)BHN*SEQ*SEQ];

// ======================= helpers =======================
__device__ __forceinline__ uint32_t smem_u32(const void* p) {
    uint32_t a;
    asm("{ .reg .u64 t; cvta.to.shared.u64 t, %1; cvt.u32.u64 %0, t; }" : "=r"(a) : "l"(p));
    return a;
}
#define CP16(dst, src) \
    asm volatile("cp.async.cg.shared.global [%0], [%1], 16;" :: "r"(dst), "l"(src))
#define CP_COMMIT() asm volatile("cp.async.commit_group;" ::: "memory")
#define CP_WAIT0()  asm volatile("cp.async.wait_group 0;" ::: "memory")

#define LDSM4(r0, r1, r2, r3, a) \
    asm volatile("ldmatrix.sync.aligned.m8n8.x4.shared.b16 {%0,%1,%2,%3}, [%4];" \
        : "=r"(r0), "=r"(r1), "=r"(r2), "=r"(r3) : "r"(a))

#define MMA16816(d, a, b) \
    asm volatile("mma.sync.aligned.m16n8k16.row.col.f32.bf16.bf16.f32 " \
        "{%0,%1,%2,%3}, {%4,%5,%6,%7}, {%8,%9}, {%0,%1,%2,%3};" \
        : "+f"((d)[0]), "+f"((d)[1]), "+f"((d)[2]), "+f"((d)[3]) \
        : "r"((a)[0]), "r"((a)[1]), "r"((a)[2]), "r"((a)[3]), \
          "r"((b)[0]), "r"((b)[1]))

__device__ __forceinline__ void split2(float v, bf16& h, bf16& l) {
    h = __float2bfloat16_rn(v);
    l = __float2bfloat16_rn(v - __bfloat162float(h));
}
__device__ __forceinline__ uint32_t pack2(float a, float b) {
    __nv_bfloat162 p; p.x = __float2bfloat16_rn(a); p.y = __float2bfloat16_rn(b);
    return *reinterpret_cast<uint32_t*>(&p);
}

// ======================= prep kernels =======================
__global__ void k_split(const float* __restrict__ in, bf16* __restrict__ oh,
                        bf16* __restrict__ ol, int n)
{
    int i = blockIdx.x * 256 + threadIdx.x;
    if (i < n) { bf16 h, l; split2(in[i], h, l); oh[i] = h; ol[i] = l; }
}

__global__ void k_tsplit(const float* __restrict__ in, bf16* __restrict__ oh,
                         bf16* __restrict__ ol, int R, int C,
                         size_t inz, size_t outz)
{
    in += (size_t)blockIdx.z * inz;
    oh += (size_t)blockIdx.z * outz;
    ol += (size_t)blockIdx.z * outz;
    __shared__ float t[32][33];
    int c0 = blockIdx.x * 32, r0 = blockIdx.y * 32;
    int tx = threadIdx.x, ty = threadIdx.y;   // (32, 8)
#pragma unroll
    for (int i = 0; i < 4; ++i)
        t[ty + i * 8][tx] = in[(size_t)(r0 + ty + i * 8) * C + c0 + tx];
    __syncthreads();
#pragma unroll
    for (int i = 0; i < 4; ++i) {
        float v = t[tx][ty + i * 8];
        bf16 h, l; split2(v, h, l);
        size_t o = (size_t)(c0 + ty + i * 8) * R + r0 + tx;
        oh[o] = h; ol[o] = l;
    }
}

// ======================= warp-MMA GEMM (bf16 3-product split) =======================
// MODE 0: proj  -> permuted bf16-split store (Q or K)
// MODE 1: scores-> fp32 * 1/16 to probs
// MODE 2: pv    -> A is fp32 probs (split on the fly); bf16-split store to att
// MODE 3: wv    -> fp32 + residual to Z
#define SMEM_BYTES 65536   // single stage: (Ah,Al,Bh,Bl) x 16KB

template<int MODE>
__global__ void __launch_bounds__(256, 2)
k_mma(const bf16* __restrict__ Ah, const bf16* __restrict__ Al,
      const bf16* __restrict__ Bh, const bf16* __restrict__ Bl,
      const float* __restrict__ Af,
      int lda, int ldb, int K,
      size_t strideAz, size_t strideBz, int bShift,
      float* __restrict__ ep_f, bf16* __restrict__ ep_h, bf16* __restrict__ ep_l,
      const float* __restrict__ resid, size_t strideEz)
{
    extern __shared__ __align__(1024) char smem[];
    const int tid = threadIdx.x;
    const int wid = tid >> 5, lane = tid & 31;
    const int wm = wid >> 2, wn = wid & 3;          // 2 x 4 warp grid
    const int mBase = blockIdx.y * 128, nBase = blockIdx.x * 128;
    const int z = blockIdx.z;

    const bf16* A0 = (MODE == 2) ? nullptr : Ah + (size_t)z * strideAz;
    const bf16* A1 = (MODE == 2) ? nullptr : Al + (size_t)z * strideAz;
    const float* AF = (MODE == 2) ? Af + (size_t)z * strideAz : nullptr;
    const bf16* B0 = Bh + (size_t)(z >> bShift) * strideBz;
    const bf16* B1 = Bl + (size_t)(z >> bShift) * strideBz;

    const int nch = K >> 6;   // Kc = 64

    const uint32_t sb  = smem_u32(smem);
    const uint32_t sAh = sb, sAl = sb + 16384, sBh = sb + 32768, sBl = sb + 49152;

    // ldmatrix per-lane geometry
    const int lrow = (lane & 7) + ((lane >> 3) & 1) * 8;
    const int kh16 = ((lane >> 4) & 1) * 16;
    const int swz  = (lane & 7) << 4;
    int rA[4], rB[2];
#pragma unroll
    for (int bm = 0; bm < 4; ++bm) rA[bm] = (wm * 64 + bm * 16 + lrow) * 128;
#pragma unroll
    for (int nb = 0; nb < 2; ++nb) rB[nb] = (wn * 32 + nb * 16 + lrow) * 128;

    float acc[4][4][4];
#pragma unroll
    for (int a = 0; a < 4; ++a)
#pragma unroll
        for (int b = 0; b < 4; ++b)
#pragma unroll
            for (int c = 0; c < 4; ++c) acc[a][b][c] = 0.f;

    for (int i = 0; i < nch; ++i) {
        const int k0 = i * 64;

        // ---------------- load phase (single stage) ----------------
        if (MODE == 2) {
            // B tiles via cp.async
#pragma unroll
            for (int t_ = 0; t_ < 2; ++t_) {
                const bf16* s_ = t_ ? B1 : B0;
                const uint32_t d0_ = t_ ? sBl : sBh;
#pragma unroll
                for (int j_ = 0; j_ < 4; ++j_) {
                    int idx_ = tid + 256 * j_;
                    int row_ = idx_ >> 3, c16_ = idx_ & 7;
                    const bf16* g_ = s_ + (size_t)(nBase + row_) * ldb + k0 + c16_ * 8;
                    uint32_t d_ = d0_ + row_ * 128 + ((c16_ * 16) ^ ((row_ & 7) << 4));
                    CP16(d_, g_);
                }
            }
            CP_COMMIT();
            // A tile: fp32 probs -> bf16 hi/lo split into smem
#pragma unroll
            for (int j_ = 0; j_ < 8; ++j_) {
                int idx_ = tid + 256 * j_;       // 2048 float4s = 128 rows x 16
                int row_ = idx_ >> 4, c4_ = idx_ & 15;
                float4 v = *reinterpret_cast<const float4*>(
                    AF + (size_t)(mBase + row_) * lda + k0 + c4_ * 4);
                bf16 hx, lx, hy, ly, hz, lz, hw, lw;
                split2(v.x, hx, lx); split2(v.y, hy, ly);
                split2(v.z, hz, lz); split2(v.w, hw, lw);
                __nv_bfloat162 h01; h01.x = hx; h01.y = hy;
                __nv_bfloat162 h23; h23.x = hz; h23.y = hw;
                __nv_bfloat162 l01; l01.x = lx; l01.y = ly;
                __nv_bfloat162 l23; l23.x = lz; l23.y = lw;
                uint32_t off = row_ * 128 + (((c4_ >> 1) * 16) ^ ((row_ & 7) << 4))
                             + (c4_ & 1) * 8;
                uint2 hq; hq.x = *reinterpret_cast<uint32_t*>(&h01);
                hq.y = *reinterpret_cast<uint32_t*>(&h23);
                uint2 lq; lq.x = *reinterpret_cast<uint32_t*>(&l01);
                lq.y = *reinterpret_cast<uint32_t*>(&l23);
                *reinterpret_cast<uint2*>(smem + (sAh - sb) + off) = hq;
                *reinterpret_cast<uint2*>(smem + (sAl - sb) + off) = lq;
            }
            CP_WAIT0();
        } else {
            const bf16* srcs_[4] = {A0, A1, B0, B1};
#pragma unroll
            for (int t_ = 0; t_ < 4; ++t_) {
                const bf16* s_ = srcs_[t_];
                const int ld_ = (t_ < 2) ? lda : ldb;
                const int rb_ = (t_ < 2) ? mBase : nBase;
                const uint32_t d0_ = sb + t_ * 16384;
#pragma unroll
                for (int j_ = 0; j_ < 4; ++j_) {
                    int idx_ = tid + 256 * j_;
                    int row_ = idx_ >> 3, c16_ = idx_ & 7;
                    const bf16* g_ = s_ + (size_t)(rb_ + row_) * ld_ + k0 + c16_ * 8;
                    uint32_t d_ = d0_ + row_ * 128 + ((c16_ * 16) ^ ((row_ & 7) << 4));
                    CP16(d_, g_);
                }
            }
            CP_COMMIT();
            CP_WAIT0();
        }
        __syncthreads();

        // ---------------- compute phase ----------------
#pragma unroll
        for (int ks = 0; ks < 4; ++ks) {
            const int cz = ((ks * 32) + kh16) ^ swz;
            // product 1: Ah x Bh
            uint32_t ah[4][4];
#pragma unroll
            for (int bm = 0; bm < 4; ++bm)
                LDSM4(ah[bm][0], ah[bm][1], ah[bm][2], ah[bm][3], sAh + rA[bm] + cz);
            uint32_t bh[4][2];
#pragma unroll
            for (int nb = 0; nb < 2; ++nb) {
                uint32_t t0, t1, t2, t3;
                LDSM4(t0, t1, t2, t3, sBh + rB[nb] + cz);
                bh[nb * 2][0] = t0; bh[nb * 2][1] = t2;
                bh[nb * 2 + 1][0] = t1; bh[nb * 2 + 1][1] = t3;
            }
#pragma unroll
            for (int bm = 0; bm < 4; ++bm)
#pragma unroll
                for (int bn = 0; bn < 4; ++bn) MMA16816(acc[bm][bn], ah[bm], bh[bn]);
            // product 2: Al x Bh  (bh dies after)
            {
                uint32_t al[4][4];
#pragma unroll
                for (int bm = 0; bm < 4; ++bm)
                    LDSM4(al[bm][0], al[bm][1], al[bm][2], al[bm][3], sAl + rA[bm] + cz);
#pragma unroll
                for (int bm = 0; bm < 4; ++bm)
#pragma unroll
                    for (int bn = 0; bn < 4; ++bn) MMA16816(acc[bm][bn], al[bm], bh[bn]);
            }
            // product 3: Ah x Bl
            {
                uint32_t bl[4][2];
#pragma unroll
                for (int nb = 0; nb < 2; ++nb) {
                    uint32_t t0, t1, t2, t3;
                    LDSM4(t0, t1, t2, t3, sBl + rB[nb] + cz);
                    bl[nb * 2][0] = t0; bl[nb * 2][1] = t2;
                    bl[nb * 2 + 1][0] = t1; bl[nb * 2 + 1][1] = t3;
                }
#pragma unroll
                for (int bm = 0; bm < 4; ++bm)
#pragma unroll
                    for (int bn = 0; bn < 4; ++bn) MMA16816(acc[bm][bn], ah[bm], bl[bn]);
            }
        }
        if (i + 1 < nch) __syncthreads();
    }

    // ======================= epilogue =======================
    const int g4 = lane >> 2, t4 = lane & 3;
#pragma unroll
    for (int bm = 0; bm < 4; ++bm) {
#pragma unroll
        for (int bn = 0; bn < 4; ++bn) {
            const int r0 = mBase + wm * 64 + bm * 16 + g4;
            const int c0 = nBase + wn * 32 + bn * 8 + t4 * 2;
            const float* a4 = acc[bm][bn];
#pragma unroll
            for (int half = 0; half < 2; ++half) {
                const int gr = r0 + half * 8;
                const float v0 = a4[half * 2 + 0];
                const float v1 = a4[half * 2 + 1];
                if (MODE == 1) {
                    float2 q; q.x = v0 * 0.0625f; q.y = v1 * 0.0625f;
                    *reinterpret_cast<float2*>(
                        ep_f + (size_t)z * strideEz + (size_t)gr * SEQ + c0) = q;
                } else if (MODE == 3) {
                    size_t off = (size_t)gr * DIM + c0;
                    float2 rx = *reinterpret_cast<const float2*>(resid + off);
                    float2 q; q.x = v0 + rx.x; q.y = v1 + rx.y;
                    *reinterpret_cast<float2*>(ep_f + off) = q;
                } else if (MODE == 0) {
                    const int bb = gr >> 11, rr = gr & 2047;
                    const int hh = rr >> 9, ib = (rr & 511) << 2;
                    const int ii = ib | (c0 >> 8), dd = c0 & 255;
                    size_t base = ((size_t)(bb * 4 + hh) * SEQ + ii) * DIM + dd;
                    bf16 h0, l0, h1, l1;
                    split2(v0, h0, l0); split2(v1, h1, l1);
                    __nv_bfloat162 ph; ph.x = h0; ph.y = h1;
                    __nv_bfloat162 pl; pl.x = l0; pl.y = l1;
                    *reinterpret_cast<__nv_bfloat162*>(ep_h + base) = ph;
                    *reinterpret_cast<__nv_bfloat162*>(ep_l + base) = pl;
                } else {  // MODE 2
                    const int bb = z >> 2, h = z & 3;
                    size_t base = ((size_t)(bb * SEQ + gr)) * HD + h * DIM + c0;
                    bf16 h0, l0, h1, l1;
                    split2(v0, h0, l0); split2(v1, h1, l1);
                    __nv_bfloat162 ph; ph.x = h0; ph.y = h1;
                    __nv_bfloat162 pl; pl.x = l0; pl.y = l1;
                    *reinterpret_cast<__nv_bfloat162*>(ep_h + base) = ph;
                    *reinterpret_cast<__nv_bfloat162*>(ep_l + base) = pl;
                }
            }
        }
    }
}

// ======================= softmax (in-place, fp32 only) =======================
__global__ void k_softmax(float* __restrict__ probs)
{
    const size_t row = blockIdx.x;
    float4* p4 = reinterpret_cast<float4*>(probs + row * SEQ);
    const int t = threadIdx.x;       // 256 threads x 2 float4 = 2048
    const int wid = t >> 5, lane = t & 31;
    __shared__ float red[8];

    float4 v[2];
    v[0] = p4[t]; v[1] = p4[t + 256];
    float mx = fmaxf(fmaxf(fmaxf(v[0].x, v[0].y), fmaxf(v[0].z, v[0].w)),
                     fmaxf(fmaxf(v[1].x, v[1].y), fmaxf(v[1].z, v[1].w)));
#pragma unroll
    for (int s = 16; s > 0; s >>= 1) mx = fmaxf(mx, __shfl_xor_sync(~0u, mx, s));
    if (lane == 0) red[wid] = mx;
    __syncthreads();
    float m0 = red[lane & 7];
#pragma unroll
    for (int s = 4; s > 0; s >>= 1) m0 = fmaxf(m0, __shfl_xor_sync(~0u, m0, s));
    mx = __shfl_sync(~0u, m0, 0);

    float sum = 0.f;
#pragma unroll
    for (int q = 0; q < 2; ++q) {
        v[q].x = expf(v[q].x - mx); v[q].y = expf(v[q].y - mx);
        v[q].z = expf(v[q].z - mx); v[q].w = expf(v[q].w - mx);
        sum += v[q].x + v[q].y + v[q].z + v[q].w;
    }
#pragma unroll
    for (int s = 16; s > 0; s >>= 1) sum += __shfl_xor_sync(~0u, sum, s);
    __syncthreads();
    if (lane == 0) red[wid] = sum;
    __syncthreads();
    float s0 = red[lane & 7];
#pragma unroll
    for (int s = 4; s > 0; s >>= 1) s0 += __shfl_xor_sync(~0u, s0, s);
    const float inv = 1.0f / __shfl_sync(~0u, s0, 0);

#pragma unroll
    for (int q = 0; q < 2; ++q) {
        v[q].x *= inv; v[q].y *= inv; v[q].z *= inv; v[q].w *= inv;
    }
    p4[t] = v[0]; p4[t + 256] = v[1];
}

// ======================= LayerNorm =======================
__global__ void k_ln(const float* __restrict__ Z, const float* __restrict__ gamma,
                     const float* __restrict__ beta, float* __restrict__ outp)
{
    const int R = blockIdx.x;
    const int t = threadIdx.x;
    __shared__ float red[256];

    float zv = Z[(size_t)R * DIM + t];
    red[t] = zv; __syncthreads();
    for (int s = 128; s > 0; s >>= 1) {
        if (t < s) red[t] += red[t + s];
        __syncthreads();
    }
    float mu = red[0] * (1.0f / 256.0f);
    __syncthreads();
    float dev = zv - mu;
    red[t] = dev * dev; __syncthreads();
    for (int s = 128; s > 0; s >>= 1) {
        if (t < s) red[t] += red[t + s];
        __syncthreads();
    }
    float var = red[0] * (1.0f / 256.0f);
    outp[(size_t)R * DIM + t] = dev * rsqrtf(var + 1e-5f) * gamma[t] + beta[t];
}

// ======================= launch =======================
extern "C" void kernel_launch(void* const* d_in, const int* in_sizes, int n_in,
                              void* d_out, int out_size)
{
    const float* x     = (const float*)d_in[0];
    const float* Wq    = (const float*)d_in[1];
    const float* Wk    = (const float*)d_in[2];
    const float* Wv    = (const float*)d_in[3];
    const float* gamma = (const float*)d_in[4];
    const float* beta  = (const float*)d_in[5];

    bf16 *xh, *xl, *xTh, *xTl, *wqth, *wqtl, *wkth, *wktl, *wvth, *wvtl;
    bf16 *Qh, *Ql, *Kh, *Kl, *atth, *attl;
    float *Z, *outFb, *probsFb;
    cudaGetSymbolAddress((void**)&xh, g_xh);     cudaGetSymbolAddress((void**)&xl, g_xl);
    cudaGetSymbolAddress((void**)&xTh, g_xTh);   cudaGetSymbolAddress((void**)&xTl, g_xTl);
    cudaGetSymbolAddress((void**)&wqth, g_wqth); cudaGetSymbolAddress((void**)&wqtl, g_wqtl);
    cudaGetSymbolAddress((void**)&wkth, g_wkth); cudaGetSymbolAddress((void**)&wktl, g_wktl);
    cudaGetSymbolAddress((void**)&wvth, g_wvth); cudaGetSymbolAddress((void**)&wvtl, g_wvtl);
    cudaGetSymbolAddress((void**)&Qh, g_Qh);     cudaGetSymbolAddress((void**)&Ql, g_Ql);
    cudaGetSymbolAddress((void**)&Kh, g_Kh);     cudaGetSymbolAddress((void**)&Kl, g_Kl);
    cudaGetSymbolAddress((void**)&atth, g_atth); cudaGetSymbolAddress((void**)&attl, g_attl);
    cudaGetSymbolAddress((void**)&Z, g_Z);
    cudaGetSymbolAddress((void**)&outFb, g_out_fb);
    cudaGetSymbolAddress((void**)&probsFb, g_probs_fb);

    const long long OUT_E = (long long)BS * SEQ * DIM;
    const long long PR_E  = (long long)BHN * SEQ * SEQ;
    long long osz = out_size;
    float *outp, *probs;
    if (osz >= OUT_E + PR_E) { outp = (float*)d_out; probs = (float*)d_out + OUT_E; }
    else if (osz >= PR_E)    { probs = (float*)d_out; outp = outFb; }
    else                     { outp = (float*)d_out; probs = probsFb; }

    cudaFuncSetAttribute(k_mma<0>, cudaFuncAttributeMaxDynamicSharedMemorySize, SMEM_BYTES);
    cudaFuncSetAttribute(k_mma<1>, cudaFuncAttributeMaxDynamicSharedMemorySize, SMEM_BYTES);
    cudaFuncSetAttribute(k_mma<2>, cudaFuncAttributeMaxDynamicSharedMemorySize, SMEM_BYTES);
    cudaFuncSetAttribute(k_mma<3>, cudaFuncAttributeMaxDynamicSharedMemorySize, SMEM_BYTES);

    dim3 T(256);
    const int NX = BS * SEQ * DIM;

    // --- prep: splits & transposes ---
    k_split <<<NX / 256, T>>>(x, xh, xl, NX);
    k_tsplit<<<dim3(32, 8, 1),  dim3(32, 8)>>>(Wq, wqth, wqtl, 256, 1024, 0, 0);
    k_tsplit<<<dim3(32, 8, 1),  dim3(32, 8)>>>(Wk, wkth, wktl, 256, 1024, 0, 0);
    k_tsplit<<<dim3(8, 32, 1),  dim3(32, 8)>>>(Wv, wvth, wvtl, 1024, 256, 0, 0);
    k_tsplit<<<dim3(8, 64, 4),  dim3(32, 8)>>>(x, xTh, xTl, 2048, 256,
                                               (size_t)SEQ * DIM, (size_t)SEQ * DIM);

    // --- Q, K projections (M=8192, N=1024, K=256) ---
    k_mma<0><<<dim3(8, 64, 1), T, SMEM_BYTES>>>(xh, xl, wqth, wqtl, nullptr,
        256, 256, 256, 0, 0, 0, nullptr, Qh, Ql, nullptr, 0);
    k_mma<0><<<dim3(8, 64, 1), T, SMEM_BYTES>>>(xh, xl, wkth, wktl, nullptr,
        256, 256, 256, 0, 0, 0, nullptr, Kh, Kl, nullptr, 0);

    // --- scores (per bh: 2048x2048, K=256) ---
    k_mma<1><<<dim3(16, 16, BHN), T, SMEM_BYTES>>>(Qh, Ql, Kh, Kl, nullptr,
        256, 256, 256, (size_t)SEQ * DIM, (size_t)SEQ * DIM, 0,
        probs, nullptr, nullptr, nullptr, (size_t)SEQ * SEQ);

    // --- softmax (fp32 in-place) ---
    k_softmax<<<BHN * SEQ, T>>>(probs);

    // --- PV (per bh: 2048x256, K=2048), A = fp32 probs split on the fly ---
    k_mma<2><<<dim3(2, 16, BHN), T, SMEM_BYTES>>>(nullptr, nullptr, xTh, xTl, probs,
        2048, 2048, 2048, (size_t)SEQ * SEQ, (size_t)DIM * SEQ, 2,
        nullptr, atth, attl, nullptr, 0);

    // --- att @ Wv + x (M=8192, N=256, K=1024) ---
    k_mma<3><<<dim3(2, 64, 1), T, SMEM_BYTES>>>(atth, attl, wvth, wvtl, nullptr,
        1024, 1024, 1024, 0, 0, 0, Z, nullptr, nullptr, x, 0);

    // --- LayerNorm ---
    k_ln<<<BS * SEQ, T>>>(Z, gamma, beta, outp);
}

// round 5
// speedup vs baseline: 3.4108x; 1.1802x over previous
#include <cuda_runtime.h>
#include <cuda_bf16.h>
#include <cuda_fp16.h>
#include <cstdint>
#include <cstddef>

#define BS   4
#define SEQ  2048
#define DIM  256
#define HH   4
#define HD   1024
#define BHN  16

typedef __nv_bfloat16 bf16;

// ======================= device scratch =======================
__device__ __align__(256) bf16 g_xh  [(size_t)BS*SEQ*DIM];
__device__ __align__(256) bf16 g_xl  [(size_t)BS*SEQ*DIM];
__device__ __align__(256) __half g_xTh[(size_t)BS*DIM*SEQ];
__device__ __align__(256) __half g_xTl[(size_t)BS*DIM*SEQ];
__device__ __align__(256) bf16 g_wqth[(size_t)HD*DIM];
__device__ __align__(256) bf16 g_wqtl[(size_t)HD*DIM];
__device__ __align__(256) bf16 g_wkth[(size_t)HD*DIM];
__device__ __align__(256) bf16 g_wktl[(size_t)HD*DIM];
__device__ __align__(256) bf16 g_wvth[(size_t)DIM*HD];
__device__ __align__(256) bf16 g_wvtl[(size_t)DIM*HD];
__device__ __align__(256) bf16 g_Qh  [(size_t)BHN*SEQ*DIM];
__device__ __align__(256) bf16 g_Ql  [(size_t)BHN*SEQ*DIM];
__device__ __align__(256) bf16 g_Kh  [(size_t)BHN*SEQ*DIM];
__device__ __align__(256) bf16 g_Kl  [(size_t)BHN*SEQ*DIM];
__device__ __align__(256) __half g_Pf[(size_t)BHN*SEQ*SEQ];   // fp16 probs for PV
__device__ __align__(256) bf16 g_atth[(size_t)BS*SEQ*HD];
__device__ __align__(256) bf16 g_attl[(size_t)BS*SEQ*HD];
__device__ __align__(256) float g_Z   [(size_t)BS*SEQ*DIM];
__device__ __align__(256) float g_out_fb [(size_t)BS*SEQ*DIM];
__device__ __align__(256) float g_probs_fb[(size_t)BHN*SEQ*SEQ];

// ======================= helpers =======================
__device__ __forceinline__ uint32_t smem_u32(const void* p) {
    uint32_t a;
    asm("{ .reg .u64 t; cvta.to.shared.u64 t, %1; cvt.u32.u64 %0, t; }" : "=r"(a) : "l"(p));
    return a;
}
#define CP16(dst, src) \
    asm volatile("cp.async.cg.shared.global [%0], [%1], 16;" :: "r"(dst), "l"(src))
#define CP_COMMIT() asm volatile("cp.async.commit_group;" ::: "memory")
#define CP_WAIT0()  asm volatile("cp.async.wait_group 0;" ::: "memory")
#define CP_WAIT1()  asm volatile("cp.async.wait_group 1;" ::: "memory")

#define LDSM4(r0, r1, r2, r3, a) \
    asm volatile("ldmatrix.sync.aligned.m8n8.x4.shared.b16 {%0,%1,%2,%3}, [%4];" \
        : "=r"(r0), "=r"(r1), "=r"(r2), "=r"(r3) : "r"(a))

#define MMA_BF16(d, a, b) \
    asm volatile("mma.sync.aligned.m16n8k16.row.col.f32.bf16.bf16.f32 " \
        "{%0,%1,%2,%3}, {%4,%5,%6,%7}, {%8,%9}, {%0,%1,%2,%3};" \
        : "+f"((d)[0]), "+f"((d)[1]), "+f"((d)[2]), "+f"((d)[3]) \
        : "r"((a)[0]), "r"((a)[1]), "r"((a)[2]), "r"((a)[3]), \
          "r"((b)[0]), "r"((b)[1]))

#define MMA_FP16(d, a, b) \
    asm volatile("mma.sync.aligned.m16n8k16.row.col.f32.f16.f16.f32 " \
        "{%0,%1,%2,%3}, {%4,%5,%6,%7}, {%8,%9}, {%0,%1,%2,%3};" \
        : "+f"((d)[0]), "+f"((d)[1]), "+f"((d)[2]), "+f"((d)[3]) \
        : "r"((a)[0]), "r"((a)[1]), "r"((a)[2]), "r"((a)[3]), \
          "r"((b)[0]), "r"((b)[1]))

__device__ __forceinline__ void split2(float v, bf16& h, bf16& l) {
    h = __float2bfloat16_rn(v);
    l = __float2bfloat16_rn(v - __bfloat162float(h));
}

// ======================= fused prep kernel =======================
// blocks [0,1024): x -> bf16 split
// [1024,1280): Wq^T, [1280,1536): Wk^T, [1536,1792): Wv^T (bf16 split)
// [1792,3840): x^T per batch (fp16 split)
__global__ void k_prep(const float* __restrict__ x, const float* __restrict__ Wq,
                       const float* __restrict__ Wk, const float* __restrict__ Wv,
                       bf16* __restrict__ xh, bf16* __restrict__ xl,
                       __half* __restrict__ xTh, __half* __restrict__ xTl,
                       bf16* __restrict__ wqth, bf16* __restrict__ wqtl,
                       bf16* __restrict__ wkth, bf16* __restrict__ wktl,
                       bf16* __restrict__ wvth, bf16* __restrict__ wvtl)
{
    int b = blockIdx.x;
    const int tid = threadIdx.x;
    if (b < 1024) {
        int i0 = b * 2048 + tid;
#pragma unroll
        for (int q = 0; q < 8; ++q) {
            int i = i0 + q * 256;
            bf16 h, l; split2(x[i], h, l);
            xh[i] = h; xl[i] = l;
        }
        return;
    }
    b -= 1024;
    const float* in; int R, C, bx, by; bool hf = false;
    bf16 *ohb = nullptr, *olb = nullptr;
    __half *ohh = nullptr, *olh = nullptr;
    if (b < 256)      { in = Wq; ohb = wqth; olb = wqtl; R = 256;  C = 1024; bx = b & 31; by = b >> 5; }
    else if (b < 512) { b -= 256; in = Wk; ohb = wkth; olb = wktl; R = 256; C = 1024; bx = b & 31; by = b >> 5; }
    else if (b < 768) { b -= 512; in = Wv; ohb = wvth; olb = wvtl; R = 1024; C = 256; bx = b & 7; by = b >> 3; }
    else {
        b -= 768;
        int z = b >> 9, t = b & 511;
        in  = x + (size_t)z * SEQ * DIM;
        ohh = xTh + (size_t)z * DIM * SEQ;
        olh = xTl + (size_t)z * DIM * SEQ;
        R = 2048; C = 256; bx = t & 7; by = t >> 3; hf = true;
    }

    __shared__ float tbuf[32][33];
    const int tx = tid & 31, ty = tid >> 5;
    const int c0 = bx * 32, r0 = by * 32;
#pragma unroll
    for (int i = 0; i < 4; ++i)
        tbuf[ty + i * 8][tx] = in[(size_t)(r0 + ty + i * 8) * C + c0 + tx];
    __syncthreads();
#pragma unroll
    for (int i = 0; i < 4; ++i) {
        float v = tbuf[tx][ty + i * 8];
        size_t o = (size_t)(c0 + ty + i * 8) * R + r0 + tx;
        if (hf) {
            __half h = __float2half_rn(v);
            __half l = __float2half_rn(v - __half2float(h));
            ohh[o] = h; olh[o] = l;
        } else {
            bf16 h, l; split2(v, h, l);
            ohb[o] = h; olb[o] = l;
        }
    }
}

// ======================= warp-MMA GEMM, 3-stage cp.async pipeline, Kc=32 ==========
// MODE 0: proj   (bf16 split x bf16 split, 3 products) -> permuted bf16-split store
// MODE 1: scores (bf16 3 products) -> fp32 * 1/16 to probs
// MODE 2: pv     (fp16 single A x fp16-split B, 2 products) -> bf16-split att
// MODE 3: wv     (bf16 3 products) -> fp32 + residual
// Stage layout (64B rows, Swizzle<2,4,3>):
//   MODE!=2: [Ah 8K][Al 8K][Bh 8K][Bl 8K] = 32K
//   MODE==2: [A  8K][Bh 8K][Bl 8K]        = 24K

template<int MODE>
__global__ void __launch_bounds__(256, 2)
k_mma(const uint8_t* __restrict__ Ah, const uint8_t* __restrict__ Al,
      const uint8_t* __restrict__ Bh, const uint8_t* __restrict__ Bl,
      int lda, int ldb, int K,
      size_t strideAz, size_t strideBz, int bShift,
      float* __restrict__ ep_f, bf16* __restrict__ ep_h, bf16* __restrict__ ep_l,
      const float* __restrict__ resid, size_t strideEz)
{
    constexpr int STAGE = (MODE == 2) ? 24576 : 32768;
    extern __shared__ __align__(1024) char smem[];
    const uint32_t sb = smem_u32(smem);
    const int tid = threadIdx.x;
    const int wid = tid >> 5, lane = tid & 31;
    const int wm = wid >> 2, wn = wid & 3;          // 2 x 4 warp grid
    const int mBase = blockIdx.y * 128, nBase = blockIdx.x * 128;
    const int z = blockIdx.z;

    const uint8_t* A0 = Ah + (size_t)z * strideAz * 2;
    const uint8_t* A1 = (MODE == 2) ? nullptr : Al + (size_t)z * strideAz * 2;
    const uint8_t* B0 = Bh + (size_t)(z >> bShift) * strideBz * 2;
    const uint8_t* B1 = Bl + (size_t)(z >> bShift) * strideBz * 2;

    const int nch = K >> 5;   // Kc = 32

    // 16B-granule tile loader: 128 rows x 64B, swizzled
#define LOAD_TILE(srcB, ldE, rowB, k0, dstOff)                                        \
    { _Pragma("unroll") for (int p_ = 0; p_ < 2; ++p_) {                              \
        int idx_ = tid + 256 * p_;                                                    \
        int row_ = idx_ >> 2, c_ = idx_ & 3;                                          \
        const uint8_t* g_ = (srcB) +                                                  \
            ((size_t)((rowB) + row_) * (ldE) + (k0) + c_ * 8) * 2;                    \
        uint32_t d_ = sb + (dstOff) + row_ * 64 + ((c_ ^ ((row_ >> 1) & 3)) << 4);    \
        CP16(d_, g_); } }

#define LOAD_CHUNK(i_, s_)                                                            \
    {                                                                                 \
        const int k0_ = (i_) * 32;                                                    \
        const int so_ = (s_) * STAGE;                                                 \
        if (MODE == 2) {                                                              \
            LOAD_TILE(A0, lda, mBase, k0_, so_);                                      \
            LOAD_TILE(B0, ldb, nBase, k0_, so_ + 8192);                               \
            LOAD_TILE(B1, ldb, nBase, k0_, so_ + 16384);                              \
        } else {                                                                      \
            LOAD_TILE(A0, lda, mBase, k0_, so_);                                      \
            LOAD_TILE(A1, lda, mBase, k0_, so_ + 8192);                               \
            LOAD_TILE(B0, ldb, nBase, k0_, so_ + 16384);                              \
            LOAD_TILE(B1, ldb, nBase, k0_, so_ + 24576);                              \
        }                                                                             \
        CP_COMMIT();                                                                  \
    }

    // ldmatrix geometry (64B rows)
    const int lrow  = (lane & 7) + ((lane >> 3) & 1) * 8;
    const int khalf = (lane >> 4) & 1;
    const int swz4  = (lrow >> 1) & 3;
    int rA[4], rB[2];
#pragma unroll
    for (int bm = 0; bm < 4; ++bm) rA[bm] = (wm * 64 + bm * 16 + lrow) * 64;
#pragma unroll
    for (int nb = 0; nb < 2; ++nb) rB[nb] = (wn * 32 + nb * 16 + lrow) * 64;

    float acc[4][4][4];
#pragma unroll
    for (int a = 0; a < 4; ++a)
#pragma unroll
        for (int b = 0; b < 4; ++b)
#pragma unroll
            for (int c = 0; c < 4; ++c) acc[a][b][c] = 0.f;

    // prologue: 2 chunks in flight
    LOAD_CHUNK(0, 0);
    if (nch > 1) LOAD_CHUNK(1, 1);

    int st = 0;
    for (int i = 0; i < nch; ++i) {
        if (i + 1 < nch) { CP_WAIT1(); } else { CP_WAIT0(); }
        __syncthreads();
        if (i + 2 < nch) {
            int s2 = st + 2; if (s2 >= 3) s2 -= 3;
            LOAD_CHUNK(i + 2, s2);
        }

        const uint32_t so = sb + st * STAGE;
        const uint32_t sA  = so;
        const uint32_t sAl = so + 8192;                       // MODE!=2 only
        const uint32_t sBh = so + (MODE == 2 ? 8192 : 16384);
        const uint32_t sBl = so + (MODE == 2 ? 16384 : 24576);

#pragma unroll
        for (int ks = 0; ks < 2; ++ks) {
            const int cb = (((ks * 2 + khalf) ^ swz4) << 4);
            uint32_t ah[4][4];
#pragma unroll
            for (int bm = 0; bm < 4; ++bm)
                LDSM4(ah[bm][0], ah[bm][1], ah[bm][2], ah[bm][3], sA + rA[bm] + cb);
            uint32_t bh[4][2];
#pragma unroll
            for (int nb = 0; nb < 2; ++nb) {
                uint32_t t0, t1, t2, t3;
                LDSM4(t0, t1, t2, t3, sBh + rB[nb] + cb);
                bh[nb * 2][0] = t0; bh[nb * 2][1] = t2;
                bh[nb * 2 + 1][0] = t1; bh[nb * 2 + 1][1] = t3;
            }
            if (MODE == 2) {
#pragma unroll
                for (int bm = 0; bm < 4; ++bm)
#pragma unroll
                    for (int bn = 0; bn < 4; ++bn) MMA_FP16(acc[bm][bn], ah[bm], bh[bn]);
                uint32_t bl[4][2];
#pragma unroll
                for (int nb = 0; nb < 2; ++nb) {
                    uint32_t t0, t1, t2, t3;
                    LDSM4(t0, t1, t2, t3, sBl + rB[nb] + cb);
                    bl[nb * 2][0] = t0; bl[nb * 2][1] = t2;
                    bl[nb * 2 + 1][0] = t1; bl[nb * 2 + 1][1] = t3;
                }
#pragma unroll
                for (int bm = 0; bm < 4; ++bm)
#pragma unroll
                    for (int bn = 0; bn < 4; ++bn) MMA_FP16(acc[bm][bn], ah[bm], bl[bn]);
            } else {
#pragma unroll
                for (int bm = 0; bm < 4; ++bm)
#pragma unroll
                    for (int bn = 0; bn < 4; ++bn) MMA_BF16(acc[bm][bn], ah[bm], bh[bn]);
                {
                    uint32_t al[4][4];
#pragma unroll
                    for (int bm = 0; bm < 4; ++bm)
                        LDSM4(al[bm][0], al[bm][1], al[bm][2], al[bm][3], sAl + rA[bm] + cb);
#pragma unroll
                    for (int bm = 0; bm < 4; ++bm)
#pragma unroll
                        for (int bn = 0; bn < 4; ++bn) MMA_BF16(acc[bm][bn], al[bm], bh[bn]);
                }
                {
                    uint32_t bl[4][2];
#pragma unroll
                    for (int nb = 0; nb < 2; ++nb) {
                        uint32_t t0, t1, t2, t3;
                        LDSM4(t0, t1, t2, t3, sBl + rB[nb] + cb);
                        bl[nb * 2][0] = t0; bl[nb * 2][1] = t2;
                        bl[nb * 2 + 1][0] = t1; bl[nb * 2 + 1][1] = t3;
                    }
#pragma unroll
                    for (int bm = 0; bm < 4; ++bm)
#pragma unroll
                        for (int bn = 0; bn < 4; ++bn) MMA_BF16(acc[bm][bn], ah[bm], bl[bn]);
                }
            }
        }
        if (++st == 3) st = 0;
        if (i + 1 < nch) __syncthreads();
    }
#undef LOAD_CHUNK
#undef LOAD_TILE

    // ======================= epilogue =======================
    const int g4 = lane >> 2, t4 = lane & 3;
#pragma unroll
    for (int bm = 0; bm < 4; ++bm) {
#pragma unroll
        for (int bn = 0; bn < 4; ++bn) {
            const int r0 = mBase + wm * 64 + bm * 16 + g4;
            const int c0 = nBase + wn * 32 + bn * 8 + t4 * 2;
            const float* a4 = acc[bm][bn];
#pragma unroll
            for (int half = 0; half < 2; ++half) {
                const int gr = r0 + half * 8;
                const float v0 = a4[half * 2 + 0];
                const float v1 = a4[half * 2 + 1];
                if (MODE == 1) {
                    float2 q; q.x = v0 * 0.0625f; q.y = v1 * 0.0625f;
                    *reinterpret_cast<float2*>(
                        ep_f + (size_t)z * strideEz + (size_t)gr * SEQ + c0) = q;
                } else if (MODE == 3) {
                    size_t off = (size_t)gr * DIM + c0;
                    float2 rx = *reinterpret_cast<const float2*>(resid + off);
                    float2 q; q.x = v0 + rx.x; q.y = v1 + rx.y;
                    *reinterpret_cast<float2*>(ep_f + off) = q;
                } else if (MODE == 0) {
                    const int bb = gr >> 11, rr = gr & 2047;
                    const int hh = rr >> 9, ib = (rr & 511) << 2;
                    const int ii = ib | (c0 >> 8), dd = c0 & 255;
                    size_t base = ((size_t)(bb * 4 + hh) * SEQ + ii) * DIM + dd;
                    bf16 h0, l0, h1, l1;
                    split2(v0, h0, l0); split2(v1, h1, l1);
                    __nv_bfloat162 ph; ph.x = h0; ph.y = h1;
                    __nv_bfloat162 pl; pl.x = l0; pl.y = l1;
                    *reinterpret_cast<__nv_bfloat162*>(ep_h + base) = ph;
                    *reinterpret_cast<__nv_bfloat162*>(ep_l + base) = pl;
                } else {  // MODE 2
                    const int bb = z >> 2, h = z & 3;
                    size_t base = ((size_t)(bb * SEQ + gr)) * HD + h * DIM + c0;
                    bf16 h0, l0, h1, l1;
                    split2(v0, h0, l0); split2(v1, h1, l1);
                    __nv_bfloat162 ph; ph.x = h0; ph.y = h1;
                    __nv_bfloat162 pl; pl.x = l0; pl.y = l1;
                    *reinterpret_cast<__nv_bfloat162*>(ep_h + base) = ph;
                    *reinterpret_cast<__nv_bfloat162*>(ep_l + base) = pl;
                }
            }
        }
    }
}

// ======================= softmax (fp32 in-place + fp16 copy) =======================
__global__ void k_softmax(float* __restrict__ probs, __half* __restrict__ pf)
{
    const size_t row = blockIdx.x;
    float4* p4 = reinterpret_cast<float4*>(probs + row * SEQ);
    const int t = threadIdx.x;
    const int wid = t >> 5, lane = t & 31;
    __shared__ float red[8];

    float4 v[2];
    v[0] = p4[t]; v[1] = p4[t + 256];
    float mx = fmaxf(fmaxf(fmaxf(v[0].x, v[0].y), fmaxf(v[0].z, v[0].w)),
                     fmaxf(fmaxf(v[1].x, v[1].y), fmaxf(v[1].z, v[1].w)));
#pragma unroll
    for (int s = 16; s > 0; s >>= 1) mx = fmaxf(mx, __shfl_xor_sync(~0u, mx, s));
    if (lane == 0) red[wid] = mx;
    __syncthreads();
    float m0 = red[lane & 7];
#pragma unroll
    for (int s = 4; s > 0; s >>= 1) m0 = fmaxf(m0, __shfl_xor_sync(~0u, m0, s));
    mx = __shfl_sync(~0u, m0, 0);

    float sum = 0.f;
#pragma unroll
    for (int q = 0; q < 2; ++q) {
        v[q].x = expf(v[q].x - mx); v[q].y = expf(v[q].y - mx);
        v[q].z = expf(v[q].z - mx); v[q].w = expf(v[q].w - mx);
        sum += v[q].x + v[q].y + v[q].z + v[q].w;
    }
#pragma unroll
    for (int s = 16; s > 0; s >>= 1) sum += __shfl_xor_sync(~0u, sum, s);
    __syncthreads();
    if (lane == 0) red[wid] = sum;
    __syncthreads();
    float s0 = red[lane & 7];
#pragma unroll
    for (int s = 4; s > 0; s >>= 1) s0 += __shfl_xor_sync(~0u, s0, s);
    const float inv = 1.0f / __shfl_sync(~0u, s0, 0);

#pragma unroll
    for (int q = 0; q < 2; ++q) {
        v[q].x *= inv; v[q].y *= inv; v[q].z *= inv; v[q].w *= inv;
    }
    p4[t] = v[0]; p4[t + 256] = v[1];

    __half2* pf2 = reinterpret_cast<__half2*>(pf + row * SEQ);
    pf2[2 * t]             = __floats2half2_rn(v[0].x, v[0].y);
    pf2[2 * t + 1]         = __floats2half2_rn(v[0].z, v[0].w);
    pf2[2 * (t + 256)]     = __floats2half2_rn(v[1].x, v[1].y);
    pf2[2 * (t + 256) + 1] = __floats2half2_rn(v[1].z, v[1].w);
}

// ======================= LayerNorm =======================
__global__ void k_ln(const float* __restrict__ Z, const float* __restrict__ gamma,
                     const float* __restrict__ beta, float* __restrict__ outp)
{
    const int R = blockIdx.x;
    const int t = threadIdx.x;
    __shared__ float red[256];

    float zv = Z[(size_t)R * DIM + t];
    red[t] = zv; __syncthreads();
    for (int s = 128; s > 0; s >>= 1) {
        if (t < s) red[t] += red[t + s];
        __syncthreads();
    }
    float mu = red[0] * (1.0f / 256.0f);
    __syncthreads();
    float dev = zv - mu;
    red[t] = dev * dev; __syncthreads();
    for (int s = 128; s > 0; s >>= 1) {
        if (t < s) red[t] += red[t + s];
        __syncthreads();
    }
    float var = red[0] * (1.0f / 256.0f);
    outp[(size_t)R * DIM + t] = dev * rsqrtf(var + 1e-5f) * gamma[t] + beta[t];
}

// ======================= launch =======================
extern "C" void kernel_launch(void* const* d_in, const int* in_sizes, int n_in,
                              void* d_out, int out_size)
{
    const float* x     = (const float*)d_in[0];
    const float* Wq    = (const float*)d_in[1];
    const float* Wk    = (const float*)d_in[2];
    const float* Wv    = (const float*)d_in[3];
    const float* gamma = (const float*)d_in[4];
    const float* beta  = (const float*)d_in[5];

    bf16 *xh, *xl, *wqth, *wqtl, *wkth, *wktl, *wvth, *wvtl;
    __half *xTh, *xTl, *Pf;
    bf16 *Qh, *Ql, *Kh, *Kl, *atth, *attl;
    float *Z, *outFb, *probsFb;
    cudaGetSymbolAddress((void**)&xh, g_xh);     cudaGetSymbolAddress((void**)&xl, g_xl);
    cudaGetSymbolAddress((void**)&xTh, g_xTh);   cudaGetSymbolAddress((void**)&xTl, g_xTl);
    cudaGetSymbolAddress((void**)&wqth, g_wqth); cudaGetSymbolAddress((void**)&wqtl, g_wqtl);
    cudaGetSymbolAddress((void**)&wkth, g_wkth); cudaGetSymbolAddress((void**)&wktl, g_wktl);
    cudaGetSymbolAddress((void**)&wvth, g_wvth); cudaGetSymbolAddress((void**)&wvtl, g_wvtl);
    cudaGetSymbolAddress((void**)&Qh, g_Qh);     cudaGetSymbolAddress((void**)&Ql, g_Ql);
    cudaGetSymbolAddress((void**)&Kh, g_Kh);     cudaGetSymbolAddress((void**)&Kl, g_Kl);
    cudaGetSymbolAddress((void**)&Pf, g_Pf);
    cudaGetSymbolAddress((void**)&atth, g_atth); cudaGetSymbolAddress((void**)&attl, g_attl);
    cudaGetSymbolAddress((void**)&Z, g_Z);
    cudaGetSymbolAddress((void**)&outFb, g_out_fb);
    cudaGetSymbolAddress((void**)&probsFb, g_probs_fb);

    const long long OUT_E = (long long)BS * SEQ * DIM;
    const long long PR_E  = (long long)BHN * SEQ * SEQ;
    long long osz = out_size;
    float *outp, *probs;
    if (osz >= OUT_E + PR_E) { outp = (float*)d_out; probs = (float*)d_out + OUT_E; }
    else if (osz >= PR_E)    { probs = (float*)d_out; outp = outFb; }
    else                     { outp = (float*)d_out; probs = probsFb; }

    cudaFuncSetAttribute(k_mma<0>, cudaFuncAttributeMaxDynamicSharedMemorySize, 98304);
    cudaFuncSetAttribute(k_mma<1>, cudaFuncAttributeMaxDynamicSharedMemorySize, 98304);
    cudaFuncSetAttribute(k_mma<2>, cudaFuncAttributeMaxDynamicSharedMemorySize, 73728);
    cudaFuncSetAttribute(k_mma<3>, cudaFuncAttributeMaxDynamicSharedMemorySize, 98304);

    dim3 T(256);

    // 1: fused prep
    k_prep<<<3840, T>>>(x, Wq, Wk, Wv, xh, xl, xTh, xTl,
                        wqth, wqtl, wkth, wktl, wvth, wvtl);

    // 2,3: Q, K projections (M=8192, N=1024, K=256)
    k_mma<0><<<dim3(8, 64, 1), T, 98304>>>((const uint8_t*)xh, (const uint8_t*)xl,
        (const uint8_t*)wqth, (const uint8_t*)wqtl, 256, 256, 256,
        0, 0, 0, nullptr, Qh, Ql, nullptr, 0);
    k_mma<0><<<dim3(8, 64, 1), T, 98304>>>((const uint8_t*)xh, (const uint8_t*)xl,
        (const uint8_t*)wkth, (const uint8_t*)wktl, 256, 256, 256,
        0, 0, 0, nullptr, Kh, Kl, nullptr, 0);

    // 4: scores (per bh: 2048x2048, K=256)
    k_mma<1><<<dim3(16, 16, BHN), T, 98304>>>((const uint8_t*)Qh, (const uint8_t*)Ql,
        (const uint8_t*)Kh, (const uint8_t*)Kl, 256, 256, 256,
        (size_t)SEQ * DIM, (size_t)SEQ * DIM, 0,
        probs, nullptr, nullptr, nullptr, (size_t)SEQ * SEQ);

    // 5: softmax (fp32 + fp16 copy)
    k_softmax<<<BHN * SEQ, T>>>(probs, Pf);

    // 6 (profiled): PV (per bh: 2048x256, K=2048), fp16 2-product
    k_mma<2><<<dim3(2, 16, BHN), T, 73728>>>((const uint8_t*)Pf, nullptr,
        (const uint8_t*)xTh, (const uint8_t*)xTl, 2048, 2048, 2048,
        (size_t)SEQ * SEQ, (size_t)DIM * SEQ, 2,
        nullptr, atth, attl, nullptr, 0);

    // 7: att @ Wv + x (M=8192, N=256, K=1024)
    k_mma<3><<<dim3(2, 64, 1), T, 98304>>>((const uint8_t*)atth, (const uint8_t*)attl,
        (const uint8_t*)wvth, (const uint8_t*)wvtl, 1024, 1024, 1024,
        0, 0, 0, Z, nullptr, nullptr, x, 0);

    // 8: LayerNorm
    k_ln<<<BS * SEQ, T>>>(Z, gamma, beta, outp);
}

// round 6
// speedup vs baseline: 4.0374x; 1.1837x over previous
#include <cuda_runtime.h>
#include <cuda_bf16.h>
#include <cuda_fp16.h>
#include <cstdint>
#include <cstddef>

#define BS   4
#define SEQ  2048
#define DIM  256
#define HH   4
#define HD   1024
#define BHN  16

typedef __nv_bfloat16 bf16;

// ======================= device scratch =======================
__device__ __align__(256) bf16   g_xh  [(size_t)BS*SEQ*DIM];
__device__ __align__(256) bf16   g_xl  [(size_t)BS*SEQ*DIM];
__device__ __align__(256) __half g_xTf [(size_t)BS*DIM*SEQ];     // x^T fp16 single
__device__ __align__(256) bf16   g_wqth[(size_t)HD*DIM];
__device__ __align__(256) bf16   g_wqtl[(size_t)HD*DIM];
__device__ __align__(256) bf16   g_wkth[(size_t)HD*DIM];
__device__ __align__(256) bf16   g_wktl[(size_t)HD*DIM];
__device__ __align__(256) __half g_wvtf[(size_t)DIM*HD];         // Wv^T fp16 single
__device__ __align__(256) bf16   g_Qh  [(size_t)BHN*SEQ*DIM];
__device__ __align__(256) bf16   g_Ql  [(size_t)BHN*SEQ*DIM];
__device__ __align__(256) bf16   g_Kh  [(size_t)BHN*SEQ*DIM];
__device__ __align__(256) bf16   g_Kl  [(size_t)BHN*SEQ*DIM];
__device__ __align__(256) __half g_Pf  [(size_t)BHN*SEQ*SEQ];    // fp16 probs for PV
__device__ __align__(256) __half g_attf[(size_t)BS*SEQ*HD];      // att fp16 single
__device__ __align__(256) float  g_Z   [(size_t)BS*SEQ*DIM];
__device__ __align__(256) float  g_out_fb [(size_t)BS*SEQ*DIM];
__device__ __align__(256) float  g_probs_fb[(size_t)BHN*SEQ*SEQ];

// ======================= helpers =======================
__device__ __forceinline__ uint32_t smem_u32(const void* p) {
    uint32_t a;
    asm("{ .reg .u64 t; cvta.to.shared.u64 t, %1; cvt.u32.u64 %0, t; }" : "=r"(a) : "l"(p));
    return a;
}
#define CP16(dst, src) \
    asm volatile("cp.async.cg.shared.global [%0], [%1], 16;" :: "r"(dst), "l"(src))
#define CP_COMMIT() asm volatile("cp.async.commit_group;" ::: "memory")
#define CP_WAIT0()  asm volatile("cp.async.wait_group 0;" ::: "memory")
#define CP_WAIT1()  asm volatile("cp.async.wait_group 1;" ::: "memory")

#define LDSM4(r0, r1, r2, r3, a) \
    asm volatile("ldmatrix.sync.aligned.m8n8.x4.shared.b16 {%0,%1,%2,%3}, [%4];" \
        : "=r"(r0), "=r"(r1), "=r"(r2), "=r"(r3) : "r"(a))

#define MMA_BF16(d, a, b) \
    asm volatile("mma.sync.aligned.m16n8k16.row.col.f32.bf16.bf16.f32 " \
        "{%0,%1,%2,%3}, {%4,%5,%6,%7}, {%8,%9}, {%0,%1,%2,%3};" \
        : "+f"((d)[0]), "+f"((d)[1]), "+f"((d)[2]), "+f"((d)[3]) \
        : "r"((a)[0]), "r"((a)[1]), "r"((a)[2]), "r"((a)[3]), \
          "r"((b)[0]), "r"((b)[1]))

#define MMA_FP16(d, a, b) \
    asm volatile("mma.sync.aligned.m16n8k16.row.col.f32.f16.f16.f32 " \
        "{%0,%1,%2,%3}, {%4,%5,%6,%7}, {%8,%9}, {%0,%1,%2,%3};" \
        : "+f"((d)[0]), "+f"((d)[1]), "+f"((d)[2]), "+f"((d)[3]) \
        : "r"((a)[0]), "r"((a)[1]), "r"((a)[2]), "r"((a)[3]), \
          "r"((b)[0]), "r"((b)[1]))

__device__ __forceinline__ void split2(float v, bf16& h, bf16& l) {
    h = __float2bfloat16_rn(v);
    l = __float2bfloat16_rn(v - __bfloat162float(h));
}

// ======================= fused prep kernel =======================
// blocks [0,1024): x -> bf16 split
// [1024,1280): Wq^T bf16 split, [1280,1536): Wk^T bf16 split
// [1536,1792): Wv^T fp16 single
// [1792,3840): x^T per batch fp16 single
__global__ void k_prep(const float* __restrict__ x, const float* __restrict__ Wq,
                       const float* __restrict__ Wk, const float* __restrict__ Wv,
                       bf16* __restrict__ xh, bf16* __restrict__ xl,
                       __half* __restrict__ xTf,
                       bf16* __restrict__ wqth, bf16* __restrict__ wqtl,
                       bf16* __restrict__ wkth, bf16* __restrict__ wktl,
                       __half* __restrict__ wvtf)
{
    int b = blockIdx.x;
    const int tid = threadIdx.x;
    if (b < 1024) {
        int i0 = b * 2048 + tid;
#pragma unroll
        for (int q = 0; q < 8; ++q) {
            int i = i0 + q * 256;
            bf16 h, l; split2(x[i], h, l);
            xh[i] = h; xl[i] = l;
        }
        return;
    }
    b -= 1024;
    const float* in; int R, C, bx, by; bool hf = false;
    bf16 *ohb = nullptr, *olb = nullptr;
    __half *ohh = nullptr;
    if (b < 256)      { in = Wq; ohb = wqth; olb = wqtl; R = 256;  C = 1024; bx = b & 31; by = b >> 5; }
    else if (b < 512) { b -= 256; in = Wk; ohb = wkth; olb = wktl; R = 256; C = 1024; bx = b & 31; by = b >> 5; }
    else if (b < 768) { b -= 512; in = Wv; ohh = wvtf; R = 1024; C = 256; bx = b & 7; by = b >> 3; hf = true; }
    else {
        b -= 768;
        int z = b >> 9, t = b & 511;
        in  = x + (size_t)z * SEQ * DIM;
        ohh = xTf + (size_t)z * DIM * SEQ;
        R = 2048; C = 256; bx = t & 7; by = t >> 3; hf = true;
    }

    __shared__ float tbuf[32][33];
    const int tx = tid & 31, ty = tid >> 5;
    const int c0 = bx * 32, r0 = by * 32;
#pragma unroll
    for (int i = 0; i < 4; ++i)
        tbuf[ty + i * 8][tx] = in[(size_t)(r0 + ty + i * 8) * C + c0 + tx];
    __syncthreads();
#pragma unroll
    for (int i = 0; i < 4; ++i) {
        float v = tbuf[tx][ty + i * 8];
        size_t o = (size_t)(c0 + ty + i * 8) * R + r0 + tx;
        if (hf) {
            ohh[o] = __float2half_rn(v);
        } else {
            bf16 h, l; split2(v, h, l);
            ohb[o] = h; olb[o] = l;
        }
    }
}

// ======================= warp-MMA GEMM, 3-stage cp.async, Kc=32 ====================
// MODE 0: proj   (bf16 4-tile, 3 products) -> permuted bf16-split store (Q or K)
// MODE 1: scores (bf16 4-tile, 3 products) -> fp32 * 1/16 to probs
// MODE 2: pv     (fp16 2-tile, 1 product)  -> fp16 single att
// MODE 3: wv     (fp16 2-tile, 1 product)  -> fp32 + residual
template<int MODE>
__global__ void __launch_bounds__(256, 2)
k_mma(const uint8_t* __restrict__ Ah, const uint8_t* __restrict__ Al,
      const uint8_t* __restrict__ Bh, const uint8_t* __restrict__ Bl,
      int lda, int ldb, int K,
      size_t strideAz, size_t strideBz, int bShift,
      float* __restrict__ ep_f, void* __restrict__ ep_a, void* __restrict__ ep_b,
      const float* __restrict__ resid, size_t strideEz)
{
    constexpr bool SPLIT = (MODE == 0 || MODE == 1);
    constexpr int STAGE = SPLIT ? 32768 : 16384;
    extern __shared__ __align__(1024) char smem[];
    const uint32_t sb = smem_u32(smem);
    const int tid = threadIdx.x;
    const int wid = tid >> 5, lane = tid & 31;
    const int wm = wid >> 2, wn = wid & 3;          // 2 x 4 warp grid
    const int mBase = blockIdx.y * 128, nBase = blockIdx.x * 128;
    const int z = blockIdx.z;

    const uint8_t* A0 = Ah + (size_t)z * strideAz * 2;
    const uint8_t* A1 = SPLIT ? Al + (size_t)z * strideAz * 2 : nullptr;
    const uint8_t* B0 = Bh + (size_t)(z >> bShift) * strideBz * 2;
    const uint8_t* B1 = SPLIT ? Bl + (size_t)(z >> bShift) * strideBz * 2 : nullptr;

    const int nch = K >> 5;   // Kc = 32

#define LOAD_TILE(srcB, ldE, rowB, k0, dstOff)                                        \
    { _Pragma("unroll") for (int p_ = 0; p_ < 2; ++p_) {                              \
        int idx_ = tid + 256 * p_;                                                    \
        int row_ = idx_ >> 2, c_ = idx_ & 3;                                          \
        const uint8_t* g_ = (srcB) +                                                  \
            ((size_t)((rowB) + row_) * (ldE) + (k0) + c_ * 8) * 2;                    \
        uint32_t d_ = sb + (dstOff) + row_ * 64 + ((c_ ^ ((row_ >> 1) & 3)) << 4);    \
        CP16(d_, g_); } }

#define LOAD_CHUNK(i_, s_)                                                            \
    {                                                                                 \
        const int k0_ = (i_) * 32;                                                    \
        const int so_ = (s_) * STAGE;                                                 \
        if (SPLIT) {                                                                  \
            LOAD_TILE(A0, lda, mBase, k0_, so_);                                      \
            LOAD_TILE(A1, lda, mBase, k0_, so_ + 8192);                               \
            LOAD_TILE(B0, ldb, nBase, k0_, so_ + 16384);                              \
            LOAD_TILE(B1, ldb, nBase, k0_, so_ + 24576);                              \
        } else {                                                                      \
            LOAD_TILE(A0, lda, mBase, k0_, so_);                                      \
            LOAD_TILE(B0, ldb, nBase, k0_, so_ + 8192);                               \
        }                                                                             \
        CP_COMMIT();                                                                  \
    }

    // ldmatrix geometry (64B rows)
    const int lrow  = (lane & 7) + ((lane >> 3) & 1) * 8;
    const int khalf = (lane >> 4) & 1;
    const int swz4  = (lrow >> 1) & 3;
    int rA[4], rB[2];
#pragma unroll
    for (int bm = 0; bm < 4; ++bm) rA[bm] = (wm * 64 + bm * 16 + lrow) * 64;
#pragma unroll
    for (int nb = 0; nb < 2; ++nb) rB[nb] = (wn * 32 + nb * 16 + lrow) * 64;

    float acc[4][4][4];
#pragma unroll
    for (int a = 0; a < 4; ++a)
#pragma unroll
        for (int b = 0; b < 4; ++b)
#pragma unroll
            for (int c = 0; c < 4; ++c) acc[a][b][c] = 0.f;

    LOAD_CHUNK(0, 0);
    if (nch > 1) LOAD_CHUNK(1, 1);

    int st = 0;
    for (int i = 0; i < nch; ++i) {
        if (i + 1 < nch) { CP_WAIT1(); } else { CP_WAIT0(); }
        __syncthreads();
        if (i + 2 < nch) {
            int s2 = st + 2; if (s2 >= 3) s2 -= 3;
            LOAD_CHUNK(i + 2, s2);
        }

        const uint32_t so = sb + st * STAGE;
        const uint32_t sA  = so;
        const uint32_t sAl = so + 8192;
        const uint32_t sBh = so + (SPLIT ? 16384 : 8192);
        const uint32_t sBl = so + 24576;

#pragma unroll
        for (int ks = 0; ks < 2; ++ks) {
            const int cb = (((ks * 2 + khalf) ^ swz4) << 4);
            uint32_t ah[4][4];
#pragma unroll
            for (int bm = 0; bm < 4; ++bm)
                LDSM4(ah[bm][0], ah[bm][1], ah[bm][2], ah[bm][3], sA + rA[bm] + cb);
            uint32_t bh[4][2];
#pragma unroll
            for (int nb = 0; nb < 2; ++nb) {
                uint32_t t0, t1, t2, t3;
                LDSM4(t0, t1, t2, t3, sBh + rB[nb] + cb);
                bh[nb * 2][0] = t0; bh[nb * 2][1] = t2;
                bh[nb * 2 + 1][0] = t1; bh[nb * 2 + 1][1] = t3;
            }
            if (!SPLIT) {
#pragma unroll
                for (int bm = 0; bm < 4; ++bm)
#pragma unroll
                    for (int bn = 0; bn < 4; ++bn) MMA_FP16(acc[bm][bn], ah[bm], bh[bn]);
            } else {
#pragma unroll
                for (int bm = 0; bm < 4; ++bm)
#pragma unroll
                    for (int bn = 0; bn < 4; ++bn) MMA_BF16(acc[bm][bn], ah[bm], bh[bn]);
                {
                    uint32_t al[4][4];
#pragma unroll
                    for (int bm = 0; bm < 4; ++bm)
                        LDSM4(al[bm][0], al[bm][1], al[bm][2], al[bm][3], sAl + rA[bm] + cb);
#pragma unroll
                    for (int bm = 0; bm < 4; ++bm)
#pragma unroll
                        for (int bn = 0; bn < 4; ++bn) MMA_BF16(acc[bm][bn], al[bm], bh[bn]);
                }
                {
                    uint32_t bl[4][2];
#pragma unroll
                    for (int nb = 0; nb < 2; ++nb) {
                        uint32_t t0, t1, t2, t3;
                        LDSM4(t0, t1, t2, t3, sBl + rB[nb] + cb);
                        bl[nb * 2][0] = t0; bl[nb * 2][1] = t2;
                        bl[nb * 2 + 1][0] = t1; bl[nb * 2 + 1][1] = t3;
                    }
#pragma unroll
                    for (int bm = 0; bm < 4; ++bm)
#pragma unroll
                        for (int bn = 0; bn < 4; ++bn) MMA_BF16(acc[bm][bn], ah[bm], bl[bn]);
                }
            }
        }
        if (++st == 3) st = 0;
        if (i + 1 < nch) __syncthreads();
    }
#undef LOAD_CHUNK
#undef LOAD_TILE

    // ======================= epilogue =======================
    const int g4 = lane >> 2, t4 = lane & 3;
#pragma unroll
    for (int bm = 0; bm < 4; ++bm) {
#pragma unroll
        for (int bn = 0; bn < 4; ++bn) {
            const int r0 = mBase + wm * 64 + bm * 16 + g4;
            const int c0 = nBase + wn * 32 + bn * 8 + t4 * 2;
            const float* a4 = acc[bm][bn];
#pragma unroll
            for (int half = 0; half < 2; ++half) {
                const int gr = r0 + half * 8;
                const float v0 = a4[half * 2 + 0];
                const float v1 = a4[half * 2 + 1];
                if (MODE == 1) {
                    float2 q; q.x = v0 * 0.0625f; q.y = v1 * 0.0625f;
                    *reinterpret_cast<float2*>(
                        ep_f + (size_t)z * strideEz + (size_t)gr * SEQ + c0) = q;
                } else if (MODE == 3) {
                    size_t off = (size_t)gr * DIM + c0;
                    float2 rx = *reinterpret_cast<const float2*>(resid + off);
                    float2 q; q.x = v0 + rx.x; q.y = v1 + rx.y;
                    *reinterpret_cast<float2*>(ep_f + off) = q;
                } else if (MODE == 0) {
                    const int bb = gr >> 11, rr = gr & 2047;
                    const int hh = rr >> 9, ib = (rr & 511) << 2;
                    const int ii = ib | (c0 >> 8), dd = c0 & 255;
                    size_t base = ((size_t)(bb * 4 + hh) * SEQ + ii) * DIM + dd;
                    bf16 h0, l0, h1, l1;
                    split2(v0, h0, l0); split2(v1, h1, l1);
                    __nv_bfloat162 ph; ph.x = h0; ph.y = h1;
                    __nv_bfloat162 pl; pl.x = l0; pl.y = l1;
                    *reinterpret_cast<__nv_bfloat162*>((bf16*)ep_a + base) = ph;
                    *reinterpret_cast<__nv_bfloat162*>((bf16*)ep_b + base) = pl;
                } else {  // MODE 2: fp16 single att
                    const int bb = z >> 2, h = z & 3;
                    size_t base = ((size_t)(bb * SEQ + gr)) * HD + h * DIM + c0;
                    *reinterpret_cast<__half2*>((__half*)ep_a + base) =
                        __floats2half2_rn(v0, v1);
                }
            }
        }
    }
}

// ======================= softmax (fp32 in-place + fp16 copy) =======================
__global__ void k_softmax(float* __restrict__ probs, __half* __restrict__ pf)
{
    const size_t row = blockIdx.x;
    float4* p4 = reinterpret_cast<float4*>(probs + row * SEQ);
    const int t = threadIdx.x;
    const int wid = t >> 5, lane = t & 31;
    __shared__ float red[8];

    float4 v[2];
    v[0] = p4[t]; v[1] = p4[t + 256];
    float mx = fmaxf(fmaxf(fmaxf(v[0].x, v[0].y), fmaxf(v[0].z, v[0].w)),
                     fmaxf(fmaxf(v[1].x, v[1].y), fmaxf(v[1].z, v[1].w)));
#pragma unroll
    for (int s = 16; s > 0; s >>= 1) mx = fmaxf(mx, __shfl_xor_sync(~0u, mx, s));
    if (lane == 0) red[wid] = mx;
    __syncthreads();
    float m0 = red[lane & 7];
#pragma unroll
    for (int s = 4; s > 0; s >>= 1) m0 = fmaxf(m0, __shfl_xor_sync(~0u, m0, s));
    mx = __shfl_sync(~0u, m0, 0);

    float sum = 0.f;
#pragma unroll
    for (int q = 0; q < 2; ++q) {
        v[q].x = __expf(v[q].x - mx); v[q].y = __expf(v[q].y - mx);
        v[q].z = __expf(v[q].z - mx); v[q].w = __expf(v[q].w - mx);
        sum += v[q].x + v[q].y + v[q].z + v[q].w;
    }
#pragma unroll
    for (int s = 16; s > 0; s >>= 1) sum += __shfl_xor_sync(~0u, sum, s);
    __syncthreads();
    if (lane == 0) red[wid] = sum;
    __syncthreads();
    float s0 = red[lane & 7];
#pragma unroll
    for (int s = 4; s > 0; s >>= 1) s0 += __shfl_xor_sync(~0u, s0, s);
    const float inv = 1.0f / __shfl_sync(~0u, s0, 0);

#pragma unroll
    for (int q = 0; q < 2; ++q) {
        v[q].x *= inv; v[q].y *= inv; v[q].z *= inv; v[q].w *= inv;
    }
    p4[t] = v[0]; p4[t + 256] = v[1];

    __half2* pf2 = reinterpret_cast<__half2*>(pf + row * SEQ);
    pf2[2 * t]             = __floats2half2_rn(v[0].x, v[0].y);
    pf2[2 * t + 1]         = __floats2half2_rn(v[0].z, v[0].w);
    pf2[2 * (t + 256)]     = __floats2half2_rn(v[1].x, v[1].y);
    pf2[2 * (t + 256) + 1] = __floats2half2_rn(v[1].z, v[1].w);
}

// ======================= LayerNorm =======================
__global__ void k_ln(const float* __restrict__ Z, const float* __restrict__ gamma,
                     const float* __restrict__ beta, float* __restrict__ outp)
{
    const int R = blockIdx.x;
    const int t = threadIdx.x;
    __shared__ float red[256];

    float zv = Z[(size_t)R * DIM + t];
    red[t] = zv; __syncthreads();
    for (int s = 128; s > 0; s >>= 1) {
        if (t < s) red[t] += red[t + s];
        __syncthreads();
    }
    float mu = red[0] * (1.0f / 256.0f);
    __syncthreads();
    float dev = zv - mu;
    red[t] = dev * dev; __syncthreads();
    for (int s = 128; s > 0; s >>= 1) {
        if (t < s) red[t] += red[t + s];
        __syncthreads();
    }
    float var = red[0] * (1.0f / 256.0f);
    outp[(size_t)R * DIM + t] = dev * rsqrtf(var + 1e-5f) * gamma[t] + beta[t];
}

// ======================= launch =======================
extern "C" void kernel_launch(void* const* d_in, const int* in_sizes, int n_in,
                              void* d_out, int out_size)
{
    const float* x     = (const float*)d_in[0];
    const float* Wq    = (const float*)d_in[1];
    const float* Wk    = (const float*)d_in[2];
    const float* Wv    = (const float*)d_in[3];
    const float* gamma = (const float*)d_in[4];
    const float* beta  = (const float*)d_in[5];

    bf16 *xh, *xl, *wqth, *wqtl, *wkth, *wktl;
    __half *xTf, *wvtf, *Pf, *attf;
    bf16 *Qh, *Ql, *Kh, *Kl;
    float *Z, *outFb, *probsFb;
    cudaGetSymbolAddress((void**)&xh, g_xh);     cudaGetSymbolAddress((void**)&xl, g_xl);
    cudaGetSymbolAddress((void**)&xTf, g_xTf);
    cudaGetSymbolAddress((void**)&wqth, g_wqth); cudaGetSymbolAddress((void**)&wqtl, g_wqtl);
    cudaGetSymbolAddress((void**)&wkth, g_wkth); cudaGetSymbolAddress((void**)&wktl, g_wktl);
    cudaGetSymbolAddress((void**)&wvtf, g_wvtf);
    cudaGetSymbolAddress((void**)&Qh, g_Qh);     cudaGetSymbolAddress((void**)&Ql, g_Ql);
    cudaGetSymbolAddress((void**)&Kh, g_Kh);     cudaGetSymbolAddress((void**)&Kl, g_Kl);
    cudaGetSymbolAddress((void**)&Pf, g_Pf);
    cudaGetSymbolAddress((void**)&attf, g_attf);
    cudaGetSymbolAddress((void**)&Z, g_Z);
    cudaGetSymbolAddress((void**)&outFb, g_out_fb);
    cudaGetSymbolAddress((void**)&probsFb, g_probs_fb);

    const long long OUT_E = (long long)BS * SEQ * DIM;
    const long long PR_E  = (long long)BHN * SEQ * SEQ;
    long long osz = out_size;
    float *outp, *probs;
    if (osz >= OUT_E + PR_E) { outp = (float*)d_out; probs = (float*)d_out + OUT_E; }
    else if (osz >= PR_E)    { probs = (float*)d_out; outp = outFb; }
    else                     { outp = (float*)d_out; probs = probsFb; }

    cudaFuncSetAttribute(k_mma<0>, cudaFuncAttributeMaxDynamicSharedMemorySize, 98304);
    cudaFuncSetAttribute(k_mma<1>, cudaFuncAttributeMaxDynamicSharedMemorySize, 98304);
    cudaFuncSetAttribute(k_mma<2>, cudaFuncAttributeMaxDynamicSharedMemorySize, 49152);
    cudaFuncSetAttribute(k_mma<3>, cudaFuncAttributeMaxDynamicSharedMemorySize, 49152);

    dim3 T(256);

    // 1: fused prep
    k_prep<<<3840, T>>>(x, Wq, Wk, Wv, xh, xl, xTf,
                        wqth, wqtl, wkth, wktl, wvtf);

    // 2,3: Q, K projections (M=8192, N=1024, K=256), bf16 3-product
    k_mma<0><<<dim3(8, 64, 1), T, 98304>>>((const uint8_t*)xh, (const uint8_t*)xl,
        (const uint8_t*)wqth, (const uint8_t*)wqtl, 256, 256, 256,
        0, 0, 0, nullptr, Qh, Ql, nullptr, 0);
    k_mma<0><<<dim3(8, 64, 1), T, 98304>>>((const uint8_t*)xh, (const uint8_t*)xl,
        (const uint8_t*)wkth, (const uint8_t*)wktl, 256, 256, 256,
        0, 0, 0, nullptr, Kh, Kl, nullptr, 0);

    // 4: scores (per bh: 2048x2048, K=256), bf16 3-product
    k_mma<1><<<dim3(16, 16, BHN), T, 98304>>>((const uint8_t*)Qh, (const uint8_t*)Ql,
        (const uint8_t*)Kh, (const uint8_t*)Kl, 256, 256, 256,
        (size_t)SEQ * DIM, (size_t)SEQ * DIM, 0,
        probs, nullptr, nullptr, nullptr, (size_t)SEQ * SEQ);

    // 5: softmax (fp32 + fp16 copy)
    k_softmax<<<BHN * SEQ, T>>>(probs, Pf);

    // 6: PV (per bh: 2048x256, K=2048), fp16 single product
    k_mma<2><<<dim3(2, 16, BHN), T, 49152>>>((const uint8_t*)Pf, nullptr,
        (const uint8_t*)xTf, nullptr, 2048, 2048, 2048,
        (size_t)SEQ * SEQ, (size_t)DIM * SEQ, 2,
        nullptr, attf, nullptr, nullptr, 0);

    // 7: att @ Wv + x (M=8192, N=256, K=1024), fp16 single product
    k_mma<3><<<dim3(2, 64, 1), T, 49152>>>((const uint8_t*)attf, nullptr,
        (const uint8_t*)wvtf, nullptr, 1024, 1024, 1024,
        0, 0, 0, Z, nullptr, nullptr, x, 0);

    // 8: LayerNorm
    k_ln<<<BS * SEQ, T>>>(Z, gamma, beta, outp);
}

// round 7
// speedup vs baseline: 4.6409x; 1.1495x over previous
#include <cuda_runtime.h>
#include <cuda_bf16.h>
#include <cuda_fp16.h>
#include <cstdint>
#include <cstddef>

#define BS   4
#define SEQ  2048
#define DIM  256
#define HH   4
#define HD   1024
#define BHN  16

typedef __nv_bfloat16 bf16;

// ======================= device scratch =======================
__device__ __align__(256) bf16   g_xh  [(size_t)BS*SEQ*DIM];
__device__ __align__(256) bf16   g_xl  [(size_t)BS*SEQ*DIM];
__device__ __align__(256) __half g_xTf [(size_t)BS*DIM*SEQ];     // x^T fp16 single
__device__ __align__(256) bf16   g_wqth[(size_t)HD*DIM];
__device__ __align__(256) bf16   g_wqtl[(size_t)HD*DIM];
__device__ __align__(256) bf16   g_wkth[(size_t)HD*DIM];
__device__ __align__(256) bf16   g_wktl[(size_t)HD*DIM];
__device__ __align__(256) __half g_wvtf[(size_t)DIM*HD];         // Wv^T fp16 single
__device__ __align__(256) __half g_Qh  [(size_t)BHN*SEQ*DIM];    // Q fp16 split
__device__ __align__(256) __half g_Ql  [(size_t)BHN*SEQ*DIM];
__device__ __align__(256) __half g_Kf  [(size_t)BHN*SEQ*DIM];    // K fp16 single
__device__ __align__(256) __half g_Pf  [(size_t)BHN*SEQ*SEQ];    // fp16 probs for PV
__device__ __align__(256) __half g_attf[(size_t)BS*SEQ*HD];      // att fp16 single
__device__ __align__(256) float  g_Z   [(size_t)BS*SEQ*DIM];
__device__ __align__(256) float  g_out_fb [(size_t)BS*SEQ*DIM];
__device__ __align__(256) float  g_probs_fb[(size_t)BHN*SEQ*SEQ];

// ======================= helpers =======================
__device__ __forceinline__ uint32_t smem_u32(const void* p) {
    uint32_t a;
    asm("{ .reg .u64 t; cvta.to.shared.u64 t, %1; cvt.u32.u64 %0, t; }" : "=r"(a) : "l"(p));
    return a;
}
#define CP16(dst, src) \
    asm volatile("cp.async.cg.shared.global [%0], [%1], 16;" :: "r"(dst), "l"(src))
#define CP_COMMIT() asm volatile("cp.async.commit_group;" ::: "memory")
#define CP_WAIT0()  asm volatile("cp.async.wait_group 0;" ::: "memory")
#define CP_WAIT1()  asm volatile("cp.async.wait_group 1;" ::: "memory")

#define LDSM4(r0, r1, r2, r3, a) \
    asm volatile("ldmatrix.sync.aligned.m8n8.x4.shared.b16 {%0,%1,%2,%3}, [%4];" \
        : "=r"(r0), "=r"(r1), "=r"(r2), "=r"(r3) : "r"(a))

#define MMA_BF16(d, a, b) \
    asm volatile("mma.sync.aligned.m16n8k16.row.col.f32.bf16.bf16.f32 " \
        "{%0,%1,%2,%3}, {%4,%5,%6,%7}, {%8,%9}, {%0,%1,%2,%3};" \
        : "+f"((d)[0]), "+f"((d)[1]), "+f"((d)[2]), "+f"((d)[3]) \
        : "r"((a)[0]), "r"((a)[1]), "r"((a)[2]), "r"((a)[3]), \
          "r"((b)[0]), "r"((b)[1]))

#define MMA_FP16(d, a, b) \
    asm volatile("mma.sync.aligned.m16n8k16.row.col.f32.f16.f16.f32 " \
        "{%0,%1,%2,%3}, {%4,%5,%6,%7}, {%8,%9}, {%0,%1,%2,%3};" \
        : "+f"((d)[0]), "+f"((d)[1]), "+f"((d)[2]), "+f"((d)[3]) \
        : "r"((a)[0]), "r"((a)[1]), "r"((a)[2]), "r"((a)[3]), \
          "r"((b)[0]), "r"((b)[1]))

__device__ __forceinline__ void split2(float v, bf16& h, bf16& l) {
    h = __float2bfloat16_rn(v);
    l = __float2bfloat16_rn(v - __bfloat162float(h));
}
__device__ __forceinline__ void split2h(float v, __half& h, __half& l) {
    h = __float2half_rn(v);
    l = __float2half_rn(v - __half2float(h));
}

// ======================= fused prep kernel =======================
__global__ void k_prep(const float* __restrict__ x, const float* __restrict__ Wq,
                       const float* __restrict__ Wk, const float* __restrict__ Wv,
                       bf16* __restrict__ xh, bf16* __restrict__ xl,
                       __half* __restrict__ xTf,
                       bf16* __restrict__ wqth, bf16* __restrict__ wqtl,
                       bf16* __restrict__ wkth, bf16* __restrict__ wktl,
                       __half* __restrict__ wvtf)
{
    int b = blockIdx.x;
    const int tid = threadIdx.x;
    if (b < 1024) {
        int i0 = b * 2048 + tid;
#pragma unroll
        for (int q = 0; q < 8; ++q) {
            int i = i0 + q * 256;
            bf16 h, l; split2(x[i], h, l);
            xh[i] = h; xl[i] = l;
        }
        return;
    }
    b -= 1024;
    const float* in; int R, C, bx, by; bool hf = false;
    bf16 *ohb = nullptr, *olb = nullptr;
    __half *ohh = nullptr;
    if (b < 256)      { in = Wq; ohb = wqth; olb = wqtl; R = 256;  C = 1024; bx = b & 31; by = b >> 5; }
    else if (b < 512) { b -= 256; in = Wk; ohb = wkth; olb = wktl; R = 256; C = 1024; bx = b & 31; by = b >> 5; }
    else if (b < 768) { b -= 512; in = Wv; ohh = wvtf; R = 1024; C = 256; bx = b & 7; by = b >> 3; hf = true; }
    else {
        b -= 768;
        int z = b >> 9, t = b & 511;
        in  = x + (size_t)z * SEQ * DIM;
        ohh = xTf + (size_t)z * DIM * SEQ;
        R = 2048; C = 256; bx = t & 7; by = t >> 3; hf = true;
    }

    __shared__ float tbuf[32][33];
    const int tx = tid & 31, ty = tid >> 5;
    const int c0 = bx * 32, r0 = by * 32;
#pragma unroll
    for (int i = 0; i < 4; ++i)
        tbuf[ty + i * 8][tx] = in[(size_t)(r0 + ty + i * 8) * C + c0 + tx];
    __syncthreads();
#pragma unroll
    for (int i = 0; i < 4; ++i) {
        float v = tbuf[tx][ty + i * 8];
        size_t o = (size_t)(c0 + ty + i * 8) * R + r0 + tx;
        if (hf) {
            ohh[o] = __float2half_rn(v);
        } else {
            bf16 h, l; split2(v, h, l);
            ohb[o] = h; olb[o] = l;
        }
    }
}

// ======================= warp-MMA GEMM, 3-stage cp.async, Kc=32 ====================
// MODE 0: proj Q (bf16 2x2 tiles, 3 products) -> permuted fp16-SPLIT store (Qh,Ql)
// MODE 4: proj K (bf16 2x2 tiles, 3 products) -> permuted fp16 SINGLE store (Kf)
// MODE 1: scores (fp16 A-split 2 tiles + B 1 tile, 2 products) -> fp32/16 probs
// MODE 2: pv     (fp16 1x1, 1 product)  -> fp16 single att
// MODE 3: wv     (fp16 1x1, 1 product)  -> fp32 + residual
template<int MODE>
__global__ void __launch_bounds__(256, 2)
k_mma(const uint8_t* __restrict__ Ah, const uint8_t* __restrict__ Al,
      const uint8_t* __restrict__ Bh, const uint8_t* __restrict__ Bl,
      int lda, int ldb, int K,
      size_t strideAz, size_t strideBz, int bShift,
      float* __restrict__ ep_f, void* __restrict__ ep_a, void* __restrict__ ep_b,
      const float* __restrict__ resid, size_t strideEz)
{
    constexpr bool PROJ  = (MODE == 0 || MODE == 4);   // bf16 3-product
    constexpr bool SCOR  = (MODE == 1);                // fp16 2-product (A split)
    constexpr int  NT    = PROJ ? 4 : (SCOR ? 3 : 2);  // tiles per stage
    constexpr int  STAGE = NT * 8192;
    extern __shared__ __align__(1024) char smem[];
    const uint32_t sb = smem_u32(smem);
    const int tid = threadIdx.x;
    const int wid = tid >> 5, lane = tid & 31;
    const int wm = wid >> 2, wn = wid & 3;          // 2 x 4 warp grid
    const int mBase = blockIdx.y * 128, nBase = blockIdx.x * 128;
    const int z = blockIdx.z;

    const uint8_t* A0 = Ah + (size_t)z * strideAz * 2;
    const uint8_t* A1 = (PROJ || SCOR) ? Al + (size_t)z * strideAz * 2 : nullptr;
    const uint8_t* B0 = Bh + (size_t)(z >> bShift) * strideBz * 2;
    const uint8_t* B1 = PROJ ? Bl + (size_t)(z >> bShift) * strideBz * 2 : nullptr;

    const int nch = K >> 5;   // Kc = 32

#define LOAD_TILE(srcB, ldE, rowB, k0, dstOff)                                        \
    { _Pragma("unroll") for (int p_ = 0; p_ < 2; ++p_) {                              \
        int idx_ = tid + 256 * p_;                                                    \
        int row_ = idx_ >> 2, c_ = idx_ & 3;                                          \
        const uint8_t* g_ = (srcB) +                                                  \
            ((size_t)((rowB) + row_) * (ldE) + (k0) + c_ * 8) * 2;                    \
        uint32_t d_ = sb + (dstOff) + row_ * 64 + ((c_ ^ ((row_ >> 1) & 3)) << 4);    \
        CP16(d_, g_); } }

#define LOAD_CHUNK(i_, s_)                                                            \
    {                                                                                 \
        const int k0_ = (i_) * 32;                                                    \
        const int so_ = (s_) * STAGE;                                                 \
        if (PROJ) {                                                                   \
            LOAD_TILE(A0, lda, mBase, k0_, so_);                                      \
            LOAD_TILE(A1, lda, mBase, k0_, so_ + 8192);                               \
            LOAD_TILE(B0, ldb, nBase, k0_, so_ + 16384);                              \
            LOAD_TILE(B1, ldb, nBase, k0_, so_ + 24576);                              \
        } else if (SCOR) {                                                            \
            LOAD_TILE(A0, lda, mBase, k0_, so_);                                      \
            LOAD_TILE(A1, lda, mBase, k0_, so_ + 8192);                               \
            LOAD_TILE(B0, ldb, nBase, k0_, so_ + 16384);                              \
        } else {                                                                      \
            LOAD_TILE(A0, lda, mBase, k0_, so_);                                      \
            LOAD_TILE(B0, ldb, nBase, k0_, so_ + 8192);                               \
        }                                                                             \
        CP_COMMIT();                                                                  \
    }

    // ldmatrix geometry (64B rows)
    const int lrow  = (lane & 7) + ((lane >> 3) & 1) * 8;
    const int khalf = (lane >> 4) & 1;
    const int swz4  = (lrow >> 1) & 3;
    int rA[4], rB[2];
#pragma unroll
    for (int bm = 0; bm < 4; ++bm) rA[bm] = (wm * 64 + bm * 16 + lrow) * 64;
#pragma unroll
    for (int nb = 0; nb < 2; ++nb) rB[nb] = (wn * 32 + nb * 16 + lrow) * 64;

    float acc[4][4][4];
#pragma unroll
    for (int a = 0; a < 4; ++a)
#pragma unroll
        for (int b = 0; b < 4; ++b)
#pragma unroll
            for (int c = 0; c < 4; ++c) acc[a][b][c] = 0.f;

    LOAD_CHUNK(0, 0);
    if (nch > 1) LOAD_CHUNK(1, 1);

    int st = 0;
    for (int i = 0; i < nch; ++i) {
        if (i + 1 < nch) { CP_WAIT1(); } else { CP_WAIT0(); }
        __syncthreads();
        if (i + 2 < nch) {
            int s2 = st + 2; if (s2 >= 3) s2 -= 3;
            LOAD_CHUNK(i + 2, s2);
        }

        const uint32_t so = sb + st * STAGE;
        const uint32_t sA  = so;
        const uint32_t sAl = so + 8192;
        const uint32_t sBh = so + (NT - (PROJ ? 2 : 1)) * 8192;
        const uint32_t sBl = so + 24576;   // PROJ only

#pragma unroll
        for (int ks = 0; ks < 2; ++ks) {
            const int cb = (((ks * 2 + khalf) ^ swz4) << 4);
            uint32_t ah[4][4];
#pragma unroll
            for (int bm = 0; bm < 4; ++bm)
                LDSM4(ah[bm][0], ah[bm][1], ah[bm][2], ah[bm][3], sA + rA[bm] + cb);
            uint32_t bh[4][2];
#pragma unroll
            for (int nb = 0; nb < 2; ++nb) {
                uint32_t t0, t1, t2, t3;
                LDSM4(t0, t1, t2, t3, sBh + rB[nb] + cb);
                bh[nb * 2][0] = t0; bh[nb * 2][1] = t2;
                bh[nb * 2 + 1][0] = t1; bh[nb * 2 + 1][1] = t3;
            }
            if (MODE == 2 || MODE == 3) {
#pragma unroll
                for (int bm = 0; bm < 4; ++bm)
#pragma unroll
                    for (int bn = 0; bn < 4; ++bn) MMA_FP16(acc[bm][bn], ah[bm], bh[bn]);
            } else if (SCOR) {
#pragma unroll
                for (int bm = 0; bm < 4; ++bm)
#pragma unroll
                    for (int bn = 0; bn < 4; ++bn) MMA_FP16(acc[bm][bn], ah[bm], bh[bn]);
                uint32_t al[4][4];
#pragma unroll
                for (int bm = 0; bm < 4; ++bm)
                    LDSM4(al[bm][0], al[bm][1], al[bm][2], al[bm][3], sAl + rA[bm] + cb);
#pragma unroll
                for (int bm = 0; bm < 4; ++bm)
#pragma unroll
                    for (int bn = 0; bn < 4; ++bn) MMA_FP16(acc[bm][bn], al[bm], bh[bn]);
            } else {  // PROJ: bf16 3-product
#pragma unroll
                for (int bm = 0; bm < 4; ++bm)
#pragma unroll
                    for (int bn = 0; bn < 4; ++bn) MMA_BF16(acc[bm][bn], ah[bm], bh[bn]);
                {
                    uint32_t al[4][4];
#pragma unroll
                    for (int bm = 0; bm < 4; ++bm)
                        LDSM4(al[bm][0], al[bm][1], al[bm][2], al[bm][3], sAl + rA[bm] + cb);
#pragma unroll
                    for (int bm = 0; bm < 4; ++bm)
#pragma unroll
                        for (int bn = 0; bn < 4; ++bn) MMA_BF16(acc[bm][bn], al[bm], bh[bn]);
                }
                {
                    uint32_t bl[4][2];
#pragma unroll
                    for (int nb = 0; nb < 2; ++nb) {
                        uint32_t t0, t1, t2, t3;
                        LDSM4(t0, t1, t2, t3, sBl + rB[nb] + cb);
                        bl[nb * 2][0] = t0; bl[nb * 2][1] = t2;
                        bl[nb * 2 + 1][0] = t1; bl[nb * 2 + 1][1] = t3;
                    }
#pragma unroll
                    for (int bm = 0; bm < 4; ++bm)
#pragma unroll
                        for (int bn = 0; bn < 4; ++bn) MMA_BF16(acc[bm][bn], ah[bm], bl[bn]);
                }
            }
        }
        if (++st == 3) st = 0;
        if (i + 1 < nch) __syncthreads();
    }
#undef LOAD_CHUNK
#undef LOAD_TILE

    // ======================= epilogue =======================
    const int g4 = lane >> 2, t4 = lane & 3;
#pragma unroll
    for (int bm = 0; bm < 4; ++bm) {
#pragma unroll
        for (int bn = 0; bn < 4; ++bn) {
            const int r0 = mBase + wm * 64 + bm * 16 + g4;
            const int c0 = nBase + wn * 32 + bn * 8 + t4 * 2;
            const float* a4 = acc[bm][bn];
#pragma unroll
            for (int half = 0; half < 2; ++half) {
                const int gr = r0 + half * 8;
                const float v0 = a4[half * 2 + 0];
                const float v1 = a4[half * 2 + 1];
                if (MODE == 1) {
                    float2 q; q.x = v0 * 0.0625f; q.y = v1 * 0.0625f;
                    *reinterpret_cast<float2*>(
                        ep_f + (size_t)z * strideEz + (size_t)gr * SEQ + c0) = q;
                } else if (MODE == 3) {
                    size_t off = (size_t)gr * DIM + c0;
                    float2 rx = *reinterpret_cast<const float2*>(resid + off);
                    float2 q; q.x = v0 + rx.x; q.y = v1 + rx.y;
                    *reinterpret_cast<float2*>(ep_f + off) = q;
                } else if (MODE == 0 || MODE == 4) {
                    const int bb = gr >> 11, rr = gr & 2047;
                    const int hh = rr >> 9, ib = (rr & 511) << 2;
                    const int ii = ib | (c0 >> 8), dd = c0 & 255;
                    size_t base = ((size_t)(bb * 4 + hh) * SEQ + ii) * DIM + dd;
                    if (MODE == 0) {
                        __half h0, l0, h1, l1;
                        split2h(v0, h0, l0); split2h(v1, h1, l1);
                        __half2 ph; ph.x = h0; ph.y = h1;
                        __half2 pl; pl.x = l0; pl.y = l1;
                        *reinterpret_cast<__half2*>((__half*)ep_a + base) = ph;
                        *reinterpret_cast<__half2*>((__half*)ep_b + base) = pl;
                    } else {
                        *reinterpret_cast<__half2*>((__half*)ep_a + base) =
                            __floats2half2_rn(v0, v1);
                    }
                } else {  // MODE 2: fp16 single att
                    const int bb = z >> 2, h = z & 3;
                    size_t base = ((size_t)(bb * SEQ + gr)) * HD + h * DIM + c0;
                    *reinterpret_cast<__half2*>((__half*)ep_a + base) =
                        __floats2half2_rn(v0, v1);
                }
            }
        }
    }
}

// ======================= softmax (fp32 in-place + fp16 copy) =======================
__global__ void k_softmax(float* __restrict__ probs, __half* __restrict__ pf)
{
    const size_t row = blockIdx.x;
    float4* p4 = reinterpret_cast<float4*>(probs + row * SEQ);
    const int t = threadIdx.x;
    const int wid = t >> 5, lane = t & 31;
    __shared__ float red[8];

    float4 v[2];
    v[0] = p4[t]; v[1] = p4[t + 256];
    float mx = fmaxf(fmaxf(fmaxf(v[0].x, v[0].y), fmaxf(v[0].z, v[0].w)),
                     fmaxf(fmaxf(v[1].x, v[1].y), fmaxf(v[1].z, v[1].w)));
#pragma unroll
    for (int s = 16; s > 0; s >>= 1) mx = fmaxf(mx, __shfl_xor_sync(~0u, mx, s));
    if (lane == 0) red[wid] = mx;
    __syncthreads();
    float m0 = red[lane & 7];
#pragma unroll
    for (int s = 4; s > 0; s >>= 1) m0 = fmaxf(m0, __shfl_xor_sync(~0u, m0, s));
    mx = __shfl_sync(~0u, m0, 0);

    float sum = 0.f;
#pragma unroll
    for (int q = 0; q < 2; ++q) {
        v[q].x = __expf(v[q].x - mx); v[q].y = __expf(v[q].y - mx);
        v[q].z = __expf(v[q].z - mx); v[q].w = __expf(v[q].w - mx);
        sum += v[q].x + v[q].y + v[q].z + v[q].w;
    }
#pragma unroll
    for (int s = 16; s > 0; s >>= 1) sum += __shfl_xor_sync(~0u, sum, s);
    __syncthreads();
    if (lane == 0) red[wid] = sum;
    __syncthreads();
    float s0 = red[lane & 7];
#pragma unroll
    for (int s = 4; s > 0; s >>= 1) s0 += __shfl_xor_sync(~0u, s0, s);
    const float inv = 1.0f / __shfl_sync(~0u, s0, 0);

#pragma unroll
    for (int q = 0; q < 2; ++q) {
        v[q].x *= inv; v[q].y *= inv; v[q].z *= inv; v[q].w *= inv;
    }
    p4[t] = v[0]; p4[t + 256] = v[1];

    __half2* pf2 = reinterpret_cast<__half2*>(pf + row * SEQ);
    pf2[2 * t]             = __floats2half2_rn(v[0].x, v[0].y);
    pf2[2 * t + 1]         = __floats2half2_rn(v[0].z, v[0].w);
    pf2[2 * (t + 256)]     = __floats2half2_rn(v[1].x, v[1].y);
    pf2[2 * (t + 256) + 1] = __floats2half2_rn(v[1].z, v[1].w);
}

// ======================= LayerNorm =======================
__global__ void k_ln(const float* __restrict__ Z, const float* __restrict__ gamma,
                     const float* __restrict__ beta, float* __restrict__ outp)
{
    const int R = blockIdx.x;
    const int t = threadIdx.x;
    __shared__ float red[256];

    float zv = Z[(size_t)R * DIM + t];
    red[t] = zv; __syncthreads();
    for (int s = 128; s > 0; s >>= 1) {
        if (t < s) red[t] += red[t + s];
        __syncthreads();
    }
    float mu = red[0] * (1.0f / 256.0f);
    __syncthreads();
    float dev = zv - mu;
    red[t] = dev * dev; __syncthreads();
    for (int s = 128; s > 0; s >>= 1) {
        if (t < s) red[t] += red[t + s];
        __syncthreads();
    }
    float var = red[0] * (1.0f / 256.0f);
    outp[(size_t)R * DIM + t] = dev * rsqrtf(var + 1e-5f) * gamma[t] + beta[t];
}

// ======================= launch =======================
extern "C" void kernel_launch(void* const* d_in, const int* in_sizes, int n_in,
                              void* d_out, int out_size)
{
    const float* x     = (const float*)d_in[0];
    const float* Wq    = (const float*)d_in[1];
    const float* Wk    = (const float*)d_in[2];
    const float* Wv    = (const float*)d_in[3];
    const float* gamma = (const float*)d_in[4];
    const float* beta  = (const float*)d_in[5];

    bf16 *xh, *xl, *wqth, *wqtl, *wkth, *wktl;
    __half *xTf, *wvtf, *Qh, *Ql, *Kf, *Pf, *attf;
    float *Z, *outFb, *probsFb;
    cudaGetSymbolAddress((void**)&xh, g_xh);     cudaGetSymbolAddress((void**)&xl, g_xl);
    cudaGetSymbolAddress((void**)&xTf, g_xTf);
    cudaGetSymbolAddress((void**)&wqth, g_wqth); cudaGetSymbolAddress((void**)&wqtl, g_wqtl);
    cudaGetSymbolAddress((void**)&wkth, g_wkth); cudaGetSymbolAddress((void**)&wktl, g_wktl);
    cudaGetSymbolAddress((void**)&wvtf, g_wvtf);
    cudaGetSymbolAddress((void**)&Qh, g_Qh);     cudaGetSymbolAddress((void**)&Ql, g_Ql);
    cudaGetSymbolAddress((void**)&Kf, g_Kf);
    cudaGetSymbolAddress((void**)&Pf, g_Pf);
    cudaGetSymbolAddress((void**)&attf, g_attf);
    cudaGetSymbolAddress((void**)&Z, g_Z);
    cudaGetSymbolAddress((void**)&outFb, g_out_fb);
    cudaGetSymbolAddress((void**)&probsFb, g_probs_fb);

    const long long OUT_E = (long long)BS * SEQ * DIM;
    const long long PR_E  = (long long)BHN * SEQ * SEQ;
    long long osz = out_size;
    float *outp, *probs;
    if (osz >= OUT_E + PR_E) { outp = (float*)d_out; probs = (float*)d_out + OUT_E; }
    else if (osz >= PR_E)    { probs = (float*)d_out; outp = outFb; }
    else                     { outp = (float*)d_out; probs = probsFb; }

    cudaFuncSetAttribute(k_mma<0>, cudaFuncAttributeMaxDynamicSharedMemorySize, 98304);
    cudaFuncSetAttribute(k_mma<4>, cudaFuncAttributeMaxDynamicSharedMemorySize, 98304);
    cudaFuncSetAttribute(k_mma<1>, cudaFuncAttributeMaxDynamicSharedMemorySize, 73728);
    cudaFuncSetAttribute(k_mma<2>, cudaFuncAttributeMaxDynamicSharedMemorySize, 49152);
    cudaFuncSetAttribute(k_mma<3>, cudaFuncAttributeMaxDynamicSharedMemorySize, 49152);

    dim3 T(256);

    // 1: fused prep
    k_prep<<<3840, T>>>(x, Wq, Wk, Wv, xh, xl, xTf,
                        wqth, wqtl, wkth, wktl, wvtf);

    // 2: Q projection -> fp16 split (Qh, Ql)
    k_mma<0><<<dim3(8, 64, 1), T, 98304>>>((const uint8_t*)xh, (const uint8_t*)xl,
        (const uint8_t*)wqth, (const uint8_t*)wqtl, 256, 256, 256,
        0, 0, 0, nullptr, Qh, Ql, nullptr, 0);
    // 3: K projection -> fp16 single (Kf)
    k_mma<4><<<dim3(8, 64, 1), T, 98304>>>((const uint8_t*)xh, (const uint8_t*)xl,
        (const uint8_t*)wkth, (const uint8_t*)wktl, 256, 256, 256,
        0, 0, 0, nullptr, Kf, nullptr, nullptr, 0);

    // 4: scores (per bh: 2048x2048, K=256), fp16 2-product
    k_mma<1><<<dim3(16, 16, BHN), T, 73728>>>((const uint8_t*)Qh, (const uint8_t*)Ql,
        (const uint8_t*)Kf, nullptr, 256, 256, 256,
        (size_t)SEQ * DIM, (size_t)SEQ * DIM, 0,
        probs, nullptr, nullptr, nullptr, (size_t)SEQ * SEQ);

    // 5: softmax (fp32 + fp16 copy)
    k_softmax<<<BHN * SEQ, T>>>(probs, Pf);

    // 6: PV (per bh: 2048x256, K=2048), fp16 single product
    k_mma<2><<<dim3(2, 16, BHN), T, 49152>>>((const uint8_t*)Pf, nullptr,
        (const uint8_t*)xTf, nullptr, 2048, 2048, 2048,
        (size_t)SEQ * SEQ, (size_t)DIM * SEQ, 2,
        nullptr, attf, nullptr, nullptr, 0);

    // 7: att @ Wv + x (M=8192, N=256, K=1024), fp16 single product
    k_mma<3><<<dim3(2, 64, 1), T, 49152>>>((const uint8_t*)attf, nullptr,
        (const uint8_t*)wvtf, nullptr, 1024, 1024, 1024,
        0, 0, 0, Z, nullptr, nullptr, x, 0);

    // 8: LayerNorm
    k_ln<<<BS * SEQ, T>>>(Z, gamma, beta, outp);
}

// round 8
// speedup vs baseline: 5.4535x; 1.1751x over previous
#include <cuda_runtime.h>
#include <cuda_bf16.h>
#include <cuda_fp16.h>
#include <cstdint>
#include <cstddef>

#define BS   4
#define SEQ  2048
#define DIM  256
#define HH   4
#define HD   1024
#define BHN  16

typedef __nv_bfloat16 bf16;

// ======================= device scratch =======================
__device__ __align__(256) bf16   g_xh  [(size_t)BS*SEQ*DIM];
__device__ __align__(256) bf16   g_xl  [(size_t)BS*SEQ*DIM];
__device__ __align__(256) __half g_xTf [(size_t)BS*DIM*SEQ];     // x^T fp16 single
__device__ __align__(256) bf16   g_wqth[(size_t)HD*DIM];
__device__ __align__(256) bf16   g_wqtl[(size_t)HD*DIM];
__device__ __align__(256) bf16   g_wkth[(size_t)HD*DIM];
__device__ __align__(256) bf16   g_wktl[(size_t)HD*DIM];
__device__ __align__(256) __half g_wvtf[(size_t)DIM*HD];         // Wv^T fp16 single
__device__ __align__(256) __half g_Qf  [(size_t)BHN*SEQ*DIM];    // Q fp16 single
__device__ __align__(256) __half g_Kf  [(size_t)BHN*SEQ*DIM];    // K fp16 single
__device__ __align__(256) __half g_Pf  [(size_t)BHN*SEQ*SEQ];    // fp16 probs for PV
__device__ __align__(256) __half g_attf[(size_t)BS*SEQ*HD];      // att fp16 single
__device__ __align__(256) float  g_Z   [(size_t)BS*SEQ*DIM];
__device__ __align__(256) float  g_out_fb [(size_t)BS*SEQ*DIM];
__device__ __align__(256) float  g_probs_fb[(size_t)BHN*SEQ*SEQ];

// ======================= helpers =======================
__device__ __forceinline__ uint32_t smem_u32(const void* p) {
    uint32_t a;
    asm("{ .reg .u64 t; cvta.to.shared.u64 t, %1; cvt.u32.u64 %0, t; }" : "=r"(a) : "l"(p));
    return a;
}
#define CP16(dst, src) \
    asm volatile("cp.async.cg.shared.global [%0], [%1], 16;" :: "r"(dst), "l"(src))
#define CP_COMMIT() asm volatile("cp.async.commit_group;" ::: "memory")
#define CP_WAIT0()  asm volatile("cp.async.wait_group 0;" ::: "memory")
#define CP_WAIT1()  asm volatile("cp.async.wait_group 1;" ::: "memory")

#define LDSM4(r0, r1, r2, r3, a) \
    asm volatile("ldmatrix.sync.aligned.m8n8.x4.shared.b16 {%0,%1,%2,%3}, [%4];" \
        : "=r"(r0), "=r"(r1), "=r"(r2), "=r"(r3) : "r"(a))

#define MMA_BF16(d, a, b) \
    asm volatile("mma.sync.aligned.m16n8k16.row.col.f32.bf16.bf16.f32 " \
        "{%0,%1,%2,%3}, {%4,%5,%6,%7}, {%8,%9}, {%0,%1,%2,%3};" \
        : "+f"((d)[0]), "+f"((d)[1]), "+f"((d)[2]), "+f"((d)[3]) \
        : "r"((a)[0]), "r"((a)[1]), "r"((a)[2]), "r"((a)[3]), \
          "r"((b)[0]), "r"((b)[1]))

#define MMA_FP16(d, a, b) \
    asm volatile("mma.sync.aligned.m16n8k16.row.col.f32.f16.f16.f32 " \
        "{%0,%1,%2,%3}, {%4,%5,%6,%7}, {%8,%9}, {%0,%1,%2,%3};" \
        : "+f"((d)[0]), "+f"((d)[1]), "+f"((d)[2]), "+f"((d)[3]) \
        : "r"((a)[0]), "r"((a)[1]), "r"((a)[2]), "r"((a)[3]), \
          "r"((b)[0]), "r"((b)[1]))

__device__ __forceinline__ void split2(float v, bf16& h, bf16& l) {
    h = __float2bfloat16_rn(v);
    l = __float2bfloat16_rn(v - __bfloat162float(h));
}

// ======================= fused prep kernel =======================
__global__ void k_prep(const float* __restrict__ x, const float* __restrict__ Wq,
                       const float* __restrict__ Wk, const float* __restrict__ Wv,
                       bf16* __restrict__ xh, bf16* __restrict__ xl,
                       __half* __restrict__ xTf,
                       bf16* __restrict__ wqth, bf16* __restrict__ wqtl,
                       bf16* __restrict__ wkth, bf16* __restrict__ wktl,
                       __half* __restrict__ wvtf)
{
    int b = blockIdx.x;
    const int tid = threadIdx.x;
    if (b < 1024) {
        int i0 = b * 2048 + tid;
#pragma unroll
        for (int q = 0; q < 8; ++q) {
            int i = i0 + q * 256;
            bf16 h, l; split2(x[i], h, l);
            xh[i] = h; xl[i] = l;
        }
        return;
    }
    b -= 1024;
    const float* in; int R, C, bx, by; bool hf = false;
    bf16 *ohb = nullptr, *olb = nullptr;
    __half *ohh = nullptr;
    if (b < 256)      { in = Wq; ohb = wqth; olb = wqtl; R = 256;  C = 1024; bx = b & 31; by = b >> 5; }
    else if (b < 512) { b -= 256; in = Wk; ohb = wkth; olb = wktl; R = 256; C = 1024; bx = b & 31; by = b >> 5; }
    else if (b < 768) { b -= 512; in = Wv; ohh = wvtf; R = 1024; C = 256; bx = b & 7; by = b >> 3; hf = true; }
    else {
        b -= 768;
        int z = b >> 9, t = b & 511;
        in  = x + (size_t)z * SEQ * DIM;
        ohh = xTf + (size_t)z * DIM * SEQ;
        R = 2048; C = 256; bx = t & 7; by = t >> 3; hf = true;
    }

    __shared__ float tbuf[32][33];
    const int tx = tid & 31, ty = tid >> 5;
    const int c0 = bx * 32, r0 = by * 32;
#pragma unroll
    for (int i = 0; i < 4; ++i)
        tbuf[ty + i * 8][tx] = in[(size_t)(r0 + ty + i * 8) * C + c0 + tx];
    __syncthreads();
#pragma unroll
    for (int i = 0; i < 4; ++i) {
        float v = tbuf[tx][ty + i * 8];
        size_t o = (size_t)(c0 + ty + i * 8) * R + r0 + tx;
        if (hf) {
            ohh[o] = __float2half_rn(v);
        } else {
            bf16 h, l; split2(v, h, l);
            ohb[o] = h; olb[o] = l;
        }
    }
}

// ======================= warp-MMA GEMM, 3-stage cp.async, Kc=32 ====================
// MODE 4: proj  (bf16 2x2 tiles, 3 products) -> permuted fp16 SINGLE (Qf or Kf)
// MODE 1: scores (fp16 1x1, 1 product) -> fp32 * 1/16 to probs
// MODE 2: pv     (fp16 1x1, 1 product) -> fp16 single att
// MODE 3: wv     (fp16 1x1, 1 product) -> fp32 + residual
template<int MODE>
__global__ void __launch_bounds__(256, 2)
k_mma(const uint8_t* __restrict__ Ah, const uint8_t* __restrict__ Al,
      const uint8_t* __restrict__ Bh, const uint8_t* __restrict__ Bl,
      int lda, int ldb, int K,
      size_t strideAz, size_t strideBz, int bShift,
      float* __restrict__ ep_f, void* __restrict__ ep_a,
      const float* __restrict__ resid, size_t strideEz)
{
    constexpr bool PROJ  = (MODE == 4);      // bf16 3-product, 4 tiles
    constexpr int  NT    = PROJ ? 4 : 2;
    constexpr int  STAGE = NT * 8192;
    extern __shared__ __align__(1024) char smem[];
    const uint32_t sb = smem_u32(smem);
    const int tid = threadIdx.x;
    const int wid = tid >> 5, lane = tid & 31;
    const int wm = wid >> 2, wn = wid & 3;          // 2 x 4 warp grid
    const int mBase = blockIdx.y * 128, nBase = blockIdx.x * 128;
    const int z = blockIdx.z;

    const uint8_t* A0 = Ah + (size_t)z * strideAz * 2;
    const uint8_t* A1 = PROJ ? Al + (size_t)z * strideAz * 2 : nullptr;
    const uint8_t* B0 = Bh + (size_t)(z >> bShift) * strideBz * 2;
    const uint8_t* B1 = PROJ ? Bl + (size_t)(z >> bShift) * strideBz * 2 : nullptr;

    const int nch = K >> 5;   // Kc = 32

#define LOAD_TILE(srcB, ldE, rowB, k0, dstOff)                                        \
    { _Pragma("unroll") for (int p_ = 0; p_ < 2; ++p_) {                              \
        int idx_ = tid + 256 * p_;                                                    \
        int row_ = idx_ >> 2, c_ = idx_ & 3;                                          \
        const uint8_t* g_ = (srcB) +                                                  \
            ((size_t)((rowB) + row_) * (ldE) + (k0) + c_ * 8) * 2;                    \
        uint32_t d_ = sb + (dstOff) + row_ * 64 + ((c_ ^ ((row_ >> 1) & 3)) << 4);    \
        CP16(d_, g_); } }

#define LOAD_CHUNK(i_, s_)                                                            \
    {                                                                                 \
        const int k0_ = (i_) * 32;                                                    \
        const int so_ = (s_) * STAGE;                                                 \
        if (PROJ) {                                                                   \
            LOAD_TILE(A0, lda, mBase, k0_, so_);                                      \
            LOAD_TILE(A1, lda, mBase, k0_, so_ + 8192);                               \
            LOAD_TILE(B0, ldb, nBase, k0_, so_ + 16384);                              \
            LOAD_TILE(B1, ldb, nBase, k0_, so_ + 24576);                              \
        } else {                                                                      \
            LOAD_TILE(A0, lda, mBase, k0_, so_);                                      \
            LOAD_TILE(B0, ldb, nBase, k0_, so_ + 8192);                               \
        }                                                                             \
        CP_COMMIT();                                                                  \
    }

    // ldmatrix geometry (64B rows)
    const int lrow  = (lane & 7) + ((lane >> 3) & 1) * 8;
    const int khalf = (lane >> 4) & 1;
    const int swz4  = (lrow >> 1) & 3;
    int rA[4], rB[2];
#pragma unroll
    for (int bm = 0; bm < 4; ++bm) rA[bm] = (wm * 64 + bm * 16 + lrow) * 64;
#pragma unroll
    for (int nb = 0; nb < 2; ++nb) rB[nb] = (wn * 32 + nb * 16 + lrow) * 64;

    float acc[4][4][4];
#pragma unroll
    for (int a = 0; a < 4; ++a)
#pragma unroll
        for (int b = 0; b < 4; ++b)
#pragma unroll
            for (int c = 0; c < 4; ++c) acc[a][b][c] = 0.f;

    LOAD_CHUNK(0, 0);
    if (nch > 1) LOAD_CHUNK(1, 1);

    int st = 0;
    for (int i = 0; i < nch; ++i) {
        if (i + 1 < nch) { CP_WAIT1(); } else { CP_WAIT0(); }
        __syncthreads();
        if (i + 2 < nch) {
            int s2 = st + 2; if (s2 >= 3) s2 -= 3;
            LOAD_CHUNK(i + 2, s2);
        }

        const uint32_t so = sb + st * STAGE;
        const uint32_t sA  = so;
        const uint32_t sAl = so + 8192;                    // PROJ only
        const uint32_t sBh = so + (PROJ ? 16384 : 8192);
        const uint32_t sBl = so + 24576;                   // PROJ only

#pragma unroll
        for (int ks = 0; ks < 2; ++ks) {
            const int cb = (((ks * 2 + khalf) ^ swz4) << 4);
            uint32_t ah[4][4];
#pragma unroll
            for (int bm = 0; bm < 4; ++bm)
                LDSM4(ah[bm][0], ah[bm][1], ah[bm][2], ah[bm][3], sA + rA[bm] + cb);
            uint32_t bh[4][2];
#pragma unroll
            for (int nb = 0; nb < 2; ++nb) {
                uint32_t t0, t1, t2, t3;
                LDSM4(t0, t1, t2, t3, sBh + rB[nb] + cb);
                bh[nb * 2][0] = t0; bh[nb * 2][1] = t2;
                bh[nb * 2 + 1][0] = t1; bh[nb * 2 + 1][1] = t3;
            }
            if (!PROJ) {
#pragma unroll
                for (int bm = 0; bm < 4; ++bm)
#pragma unroll
                    for (int bn = 0; bn < 4; ++bn) MMA_FP16(acc[bm][bn], ah[bm], bh[bn]);
            } else {
#pragma unroll
                for (int bm = 0; bm < 4; ++bm)
#pragma unroll
                    for (int bn = 0; bn < 4; ++bn) MMA_BF16(acc[bm][bn], ah[bm], bh[bn]);
                {
                    uint32_t al[4][4];
#pragma unroll
                    for (int bm = 0; bm < 4; ++bm)
                        LDSM4(al[bm][0], al[bm][1], al[bm][2], al[bm][3], sAl + rA[bm] + cb);
#pragma unroll
                    for (int bm = 0; bm < 4; ++bm)
#pragma unroll
                        for (int bn = 0; bn < 4; ++bn) MMA_BF16(acc[bm][bn], al[bm], bh[bn]);
                }
                {
                    uint32_t bl[4][2];
#pragma unroll
                    for (int nb = 0; nb < 2; ++nb) {
                        uint32_t t0, t1, t2, t3;
                        LDSM4(t0, t1, t2, t3, sBl + rB[nb] + cb);
                        bl[nb * 2][0] = t0; bl[nb * 2][1] = t2;
                        bl[nb * 2 + 1][0] = t1; bl[nb * 2 + 1][1] = t3;
                    }
#pragma unroll
                    for (int bm = 0; bm < 4; ++bm)
#pragma unroll
                        for (int bn = 0; bn < 4; ++bn) MMA_BF16(acc[bm][bn], ah[bm], bl[bn]);
                }
            }
        }
        if (++st == 3) st = 0;
        if (i + 1 < nch) __syncthreads();
    }
#undef LOAD_CHUNK
#undef LOAD_TILE

    // ======================= epilogue =======================
    const int g4 = lane >> 2, t4 = lane & 3;
#pragma unroll
    for (int bm = 0; bm < 4; ++bm) {
#pragma unroll
        for (int bn = 0; bn < 4; ++bn) {
            const int r0 = mBase + wm * 64 + bm * 16 + g4;
            const int c0 = nBase + wn * 32 + bn * 8 + t4 * 2;
            const float* a4 = acc[bm][bn];
#pragma unroll
            for (int half = 0; half < 2; ++half) {
                const int gr = r0 + half * 8;
                const float v0 = a4[half * 2 + 0];
                const float v1 = a4[half * 2 + 1];
                if (MODE == 1) {
                    float2 q; q.x = v0 * 0.0625f; q.y = v1 * 0.0625f;
                    *reinterpret_cast<float2*>(
                        ep_f + (size_t)z * strideEz + (size_t)gr * SEQ + c0) = q;
                } else if (MODE == 3) {
                    size_t off = (size_t)gr * DIM + c0;
                    float2 rx = *reinterpret_cast<const float2*>(resid + off);
                    float2 q; q.x = v0 + rx.x; q.y = v1 + rx.y;
                    *reinterpret_cast<float2*>(ep_f + off) = q;
                } else if (MODE == 4) {
                    const int bb = gr >> 11, rr = gr & 2047;
                    const int hh = rr >> 9, ib = (rr & 511) << 2;
                    const int ii = ib | (c0 >> 8), dd = c0 & 255;
                    size_t base = ((size_t)(bb * 4 + hh) * SEQ + ii) * DIM + dd;
                    *reinterpret_cast<__half2*>((__half*)ep_a + base) =
                        __floats2half2_rn(v0, v1);
                } else {  // MODE 2: fp16 single att
                    const int bb = z >> 2, h = z & 3;
                    size_t base = ((size_t)(bb * SEQ + gr)) * HD + h * DIM + c0;
                    *reinterpret_cast<__half2*>((__half*)ep_a + base) =
                        __floats2half2_rn(v0, v1);
                }
            }
        }
    }
}

// ======================= softmax (fp32 in-place + fp16 copy) =======================
__global__ void k_softmax(float* __restrict__ probs, __half* __restrict__ pf)
{
    const size_t row = blockIdx.x;
    float4* p4 = reinterpret_cast<float4*>(probs + row * SEQ);
    const int t = threadIdx.x;
    const int wid = t >> 5, lane = t & 31;
    __shared__ float red[8];

    float4 v[2];
    v[0] = p4[t]; v[1] = p4[t + 256];
    float mx = fmaxf(fmaxf(fmaxf(v[0].x, v[0].y), fmaxf(v[0].z, v[0].w)),
                     fmaxf(fmaxf(v[1].x, v[1].y), fmaxf(v[1].z, v[1].w)));
#pragma unroll
    for (int s = 16; s > 0; s >>= 1) mx = fmaxf(mx, __shfl_xor_sync(~0u, mx, s));
    if (lane == 0) red[wid] = mx;
    __syncthreads();
    float m0 = red[lane & 7];
#pragma unroll
    for (int s = 4; s > 0; s >>= 1) m0 = fmaxf(m0, __shfl_xor_sync(~0u, m0, s));
    mx = __shfl_sync(~0u, m0, 0);

    float sum = 0.f;
#pragma unroll
    for (int q = 0; q < 2; ++q) {
        v[q].x = __expf(v[q].x - mx); v[q].y = __expf(v[q].y - mx);
        v[q].z = __expf(v[q].z - mx); v[q].w = __expf(v[q].w - mx);
        sum += v[q].x + v[q].y + v[q].z + v[q].w;
    }
#pragma unroll
    for (int s = 16; s > 0; s >>= 1) sum += __shfl_xor_sync(~0u, sum, s);
    __syncthreads();
    if (lane == 0) red[wid] = sum;
    __syncthreads();
    float s0 = red[lane & 7];
#pragma unroll
    for (int s = 4; s > 0; s >>= 1) s0 += __shfl_xor_sync(~0u, s0, s);
    const float inv = 1.0f / __shfl_sync(~0u, s0, 0);

#pragma unroll
    for (int q = 0; q < 2; ++q) {
        v[q].x *= inv; v[q].y *= inv; v[q].z *= inv; v[q].w *= inv;
    }
    p4[t] = v[0]; p4[t + 256] = v[1];

    __half2* pf2 = reinterpret_cast<__half2*>(pf + row * SEQ);
    pf2[2 * t]             = __floats2half2_rn(v[0].x, v[0].y);
    pf2[2 * t + 1]         = __floats2half2_rn(v[0].z, v[0].w);
    pf2[2 * (t + 256)]     = __floats2half2_rn(v[1].x, v[1].y);
    pf2[2 * (t + 256) + 1] = __floats2half2_rn(v[1].z, v[1].w);
}

// ======================= LayerNorm =======================
__global__ void k_ln(const float* __restrict__ Z, const float* __restrict__ gamma,
                     const float* __restrict__ beta, float* __restrict__ outp)
{
    const int R = blockIdx.x;
    const int t = threadIdx.x;
    __shared__ float red[256];

    float zv = Z[(size_t)R * DIM + t];
    red[t] = zv; __syncthreads();
    for (int s = 128; s > 0; s >>= 1) {
        if (t < s) red[t] += red[t + s];
        __syncthreads();
    }
    float mu = red[0] * (1.0f / 256.0f);
    __syncthreads();
    float dev = zv - mu;
    red[t] = dev * dev; __syncthreads();
    for (int s = 128; s > 0; s >>= 1) {
        if (t < s) red[t] += red[t + s];
        __syncthreads();
    }
    float var = red[0] * (1.0f / 256.0f);
    outp[(size_t)R * DIM + t] = dev * rsqrtf(var + 1e-5f) * gamma[t] + beta[t];
}

// ======================= launch =======================
extern "C" void kernel_launch(void* const* d_in, const int* in_sizes, int n_in,
                              void* d_out, int out_size)
{
    const float* x     = (const float*)d_in[0];
    const float* Wq    = (const float*)d_in[1];
    const float* Wk    = (const float*)d_in[2];
    const float* Wv    = (const float*)d_in[3];
    const float* gamma = (const float*)d_in[4];
    const float* beta  = (const float*)d_in[5];

    bf16 *xh, *xl, *wqth, *wqtl, *wkth, *wktl;
    __half *xTf, *wvtf, *Qf, *Kf, *Pf, *attf;
    float *Z, *outFb, *probsFb;
    cudaGetSymbolAddress((void**)&xh, g_xh);     cudaGetSymbolAddress((void**)&xl, g_xl);
    cudaGetSymbolAddress((void**)&xTf, g_xTf);
    cudaGetSymbolAddress((void**)&wqth, g_wqth); cudaGetSymbolAddress((void**)&wqtl, g_wqtl);
    cudaGetSymbolAddress((void**)&wkth, g_wkth); cudaGetSymbolAddress((void**)&wktl, g_wktl);
    cudaGetSymbolAddress((void**)&wvtf, g_wvtf);
    cudaGetSymbolAddress((void**)&Qf, g_Qf);     cudaGetSymbolAddress((void**)&Kf, g_Kf);
    cudaGetSymbolAddress((void**)&Pf, g_Pf);
    cudaGetSymbolAddress((void**)&attf, g_attf);
    cudaGetSymbolAddress((void**)&Z, g_Z);
    cudaGetSymbolAddress((void**)&outFb, g_out_fb);
    cudaGetSymbolAddress((void**)&probsFb, g_probs_fb);

    const long long OUT_E = (long long)BS * SEQ * DIM;
    const long long PR_E  = (long long)BHN * SEQ * SEQ;
    long long osz = out_size;
    float *outp, *probs;
    if (osz >= OUT_E + PR_E) { outp = (float*)d_out; probs = (float*)d_out + OUT_E; }
    else if (osz >= PR_E)    { probs = (float*)d_out; outp = outFb; }
    else                     { outp = (float*)d_out; probs = probsFb; }

    cudaFuncSetAttribute(k_mma<4>, cudaFuncAttributeMaxDynamicSharedMemorySize, 98304);
    cudaFuncSetAttribute(k_mma<1>, cudaFuncAttributeMaxDynamicSharedMemorySize, 49152);
    cudaFuncSetAttribute(k_mma<2>, cudaFuncAttributeMaxDynamicSharedMemorySize, 49152);
    cudaFuncSetAttribute(k_mma<3>, cudaFuncAttributeMaxDynamicSharedMemorySize, 49152);

    dim3 T(256);

    // 1: fused prep
    k_prep<<<3840, T>>>(x, Wq, Wk, Wv, xh, xl, xTf,
                        wqth, wqtl, wkth, wktl, wvtf);

    // 2: Q projection -> fp16 single (Qf)
    k_mma<4><<<dim3(8, 64, 1), T, 98304>>>((const uint8_t*)xh, (const uint8_t*)xl,
        (const uint8_t*)wqth, (const uint8_t*)wqtl, 256, 256, 256,
        0, 0, 0, nullptr, Qf, nullptr, 0);
    // 3: K projection -> fp16 single (Kf)
    k_mma<4><<<dim3(8, 64, 1), T, 98304>>>((const uint8_t*)xh, (const uint8_t*)xl,
        (const uint8_t*)wkth, (const uint8_t*)wktl, 256, 256, 256,
        0, 0, 0, nullptr, Kf, nullptr, 0);

    // 4: scores (per bh: 2048x2048, K=256), fp16 1-product
    k_mma<1><<<dim3(16, 16, BHN), T, 49152>>>((const uint8_t*)Qf, nullptr,
        (const uint8_t*)Kf, nullptr, 256, 256, 256,
        (size_t)SEQ * DIM, (size_t)SEQ * DIM, 0,
        probs, nullptr, nullptr, (size_t)SEQ * SEQ);

    // 5: softmax (fp32 + fp16 copy)
    k_softmax<<<BHN * SEQ, T>>>(probs, Pf);

    // 6: PV (per bh: 2048x256, K=2048), fp16 single product
    k_mma<2><<<dim3(2, 16, BHN), T, 49152>>>((const uint8_t*)Pf, nullptr,
        (const uint8_t*)xTf, nullptr, 2048, 2048, 2048,
        (size_t)SEQ * SEQ, (size_t)DIM * SEQ, 2,
        nullptr, attf, nullptr, 0);

    // 7: att @ Wv + x (M=8192, N=256, K=1024), fp16 single product
    k_mma<3><<<dim3(2, 64, 1), T, 49152>>>((const uint8_t*)attf, nullptr,
        (const uint8_t*)wvtf, nullptr, 1024, 1024, 1024,
        0, 0, 0, Z, nullptr, x, 0);

    // 8: LayerNorm
    k_ln<<<BS * SEQ, T>>>(Z, gamma, beta, outp);
}

// round 9
// speedup vs baseline: 5.5514x; 1.0180x over previous
#include <cuda_runtime.h>
#include <cuda_bf16.h>
#include <cuda_fp16.h>
#include <cstdint>
#include <cstddef>

#define BS   4
#define SEQ  2048
#define DIM  256
#define HH   4
#define HD   1024
#define BHN  16

typedef __nv_bfloat16 bf16;

// ======================= device scratch =======================
__device__ __align__(256) bf16   g_xh  [(size_t)BS*SEQ*DIM];
__device__ __align__(256) bf16   g_xl  [(size_t)BS*SEQ*DIM];
__device__ __align__(256) __half g_xTf [(size_t)BS*DIM*SEQ];      // x^T fp16 single
__device__ __align__(256) bf16   g_wqkth[(size_t)2*HD*DIM];       // Wq^T | Wk^T (hi)
__device__ __align__(256) bf16   g_wqktl[(size_t)2*HD*DIM];       // Wq^T | Wk^T (lo)
__device__ __align__(256) __half g_wvtf[(size_t)DIM*HD];          // Wv^T fp16 single
__device__ __align__(256) __half g_QKf [(size_t)2*BHN*SEQ*DIM];   // Qf | Kf (fp16)
__device__ __align__(256) __half g_Pf  [(size_t)BHN*SEQ*SEQ];     // fp16 probs for PV
__device__ __align__(256) __half g_attf[(size_t)BS*SEQ*HD];       // att fp16 single
__device__ __align__(256) float  g_Z   [(size_t)BS*SEQ*DIM];
__device__ __align__(256) float  g_out_fb [(size_t)BS*SEQ*DIM];
__device__ __align__(256) float  g_probs_fb[(size_t)BHN*SEQ*SEQ];

// ======================= helpers =======================
__device__ __forceinline__ uint32_t smem_u32(const void* p) {
    uint32_t a;
    asm("{ .reg .u64 t; cvta.to.shared.u64 t, %1; cvt.u32.u64 %0, t; }" : "=r"(a) : "l"(p));
    return a;
}
#define CP16(dst, src) \
    asm volatile("cp.async.cg.shared.global [%0], [%1], 16;" :: "r"(dst), "l"(src))
#define CP_COMMIT() asm volatile("cp.async.commit_group;" ::: "memory")
#define CP_WAIT0()  asm volatile("cp.async.wait_group 0;" ::: "memory")
#define CP_WAIT1()  asm volatile("cp.async.wait_group 1;" ::: "memory")
#define CP_WAIT2()  asm volatile("cp.async.wait_group 2;" ::: "memory")

#define LDSM4(r0, r1, r2, r3, a) \
    asm volatile("ldmatrix.sync.aligned.m8n8.x4.shared.b16 {%0,%1,%2,%3}, [%4];" \
        : "=r"(r0), "=r"(r1), "=r"(r2), "=r"(r3) : "r"(a))

#define MMA_BF16(d, a, b) \
    asm volatile("mma.sync.aligned.m16n8k16.row.col.f32.bf16.bf16.f32 " \
        "{%0,%1,%2,%3}, {%4,%5,%6,%7}, {%8,%9}, {%0,%1,%2,%3};" \
        : "+f"((d)[0]), "+f"((d)[1]), "+f"((d)[2]), "+f"((d)[3]) \
        : "r"((a)[0]), "r"((a)[1]), "r"((a)[2]), "r"((a)[3]), \
          "r"((b)[0]), "r"((b)[1]))

#define MMA_FP16(d, a, b) \
    asm volatile("mma.sync.aligned.m16n8k16.row.col.f32.f16.f16.f32 " \
        "{%0,%1,%2,%3}, {%4,%5,%6,%7}, {%8,%9}, {%0,%1,%2,%3};" \
        : "+f"((d)[0]), "+f"((d)[1]), "+f"((d)[2]), "+f"((d)[3]) \
        : "r"((a)[0]), "r"((a)[1]), "r"((a)[2]), "r"((a)[3]), \
          "r"((b)[0]), "r"((b)[1]))

__device__ __forceinline__ void split2(float v, bf16& h, bf16& l) {
    h = __float2bfloat16_rn(v);
    l = __float2bfloat16_rn(v - __bfloat162float(h));
}

// ======================= fused prep kernel =======================
__global__ void k_prep(const float* __restrict__ x, const float* __restrict__ Wq,
                       const float* __restrict__ Wk, const float* __restrict__ Wv,
                       bf16* __restrict__ xh, bf16* __restrict__ xl,
                       __half* __restrict__ xTf,
                       bf16* __restrict__ wqkth, bf16* __restrict__ wqktl,
                       __half* __restrict__ wvtf)
{
    int b = blockIdx.x;
    const int tid = threadIdx.x;
    if (b < 1024) {
        int i0 = b * 2048 + tid;
#pragma unroll
        for (int q = 0; q < 8; ++q) {
            int i = i0 + q * 256;
            bf16 h, l; split2(x[i], h, l);
            xh[i] = h; xl[i] = l;
        }
        return;
    }
    b -= 1024;
    const float* in; int R, C, bx, by; bool hf = false;
    bf16 *ohb = nullptr, *olb = nullptr;
    __half *ohh = nullptr;
    if (b < 256)      { in = Wq; ohb = wqkth; olb = wqktl; R = 256;  C = 1024; bx = b & 31; by = b >> 5; }
    else if (b < 512) { b -= 256; in = Wk; ohb = wqkth + (size_t)HD * DIM; olb = wqktl + (size_t)HD * DIM;
                        R = 256; C = 1024; bx = b & 31; by = b >> 5; }
    else if (b < 768) { b -= 512; in = Wv; ohh = wvtf; R = 1024; C = 256; bx = b & 7; by = b >> 3; hf = true; }
    else {
        b -= 768;
        int z = b >> 9, t = b & 511;
        in  = x + (size_t)z * SEQ * DIM;
        ohh = xTf + (size_t)z * DIM * SEQ;
        R = 2048; C = 256; bx = t & 7; by = t >> 3; hf = true;
    }

    __shared__ float tbuf[32][33];
    const int tx = tid & 31, ty = tid >> 5;
    const int c0 = bx * 32, r0 = by * 32;
#pragma unroll
    for (int i = 0; i < 4; ++i)
        tbuf[ty + i * 8][tx] = in[(size_t)(r0 + ty + i * 8) * C + c0 + tx];
    __syncthreads();
#pragma unroll
    for (int i = 0; i < 4; ++i) {
        float v = tbuf[tx][ty + i * 8];
        size_t o = (size_t)(c0 + ty + i * 8) * R + r0 + tx;
        if (hf) {
            ohh[o] = __float2half_rn(v);
        } else {
            bf16 h, l; split2(v, h, l);
            ohb[o] = h; olb[o] = l;
        }
    }
}

// ======================= warp-MMA GEMM ====================
// MODE 4: proj Q+K (bf16 3 products, 3-stage) -> permuted fp16 single (z-offset out)
// MODE 1: scores (fp16 1 product, 4-stage) -> fp32 * 1/16 to probs
// MODE 2: pv     (fp16 1 product, 4-stage) -> fp16 single att
// MODE 3: wv     (fp16 1 product, 4-stage) -> fp32 + residual
template<int MODE>
__global__ void __launch_bounds__(256, 2)
k_mma(const uint8_t* __restrict__ Ah, const uint8_t* __restrict__ Al,
      const uint8_t* __restrict__ Bh, const uint8_t* __restrict__ Bl,
      int lda, int ldb, int K,
      size_t strideAz, size_t strideBz, int bShift,
      float* __restrict__ ep_f, void* __restrict__ ep_a,
      const float* __restrict__ resid, size_t strideEz)
{
    constexpr bool PROJ   = (MODE == 4);      // bf16 3-product, 4 tiles/stage
    constexpr int  NT     = PROJ ? 4 : 2;
    constexpr int  STAGE  = NT * 8192;
    constexpr int  NSTAGE = PROJ ? 3 : 4;
    extern __shared__ __align__(1024) char smem[];
    const uint32_t sb = smem_u32(smem);
    const int tid = threadIdx.x;
    const int wid = tid >> 5, lane = tid & 31;
    const int wm = wid >> 2, wn = wid & 3;          // 2 x 4 warp grid
    const int mBase = blockIdx.y * 128, nBase = blockIdx.x * 128;
    const int z = blockIdx.z;

    const uint8_t* A0 = Ah + (size_t)z * strideAz * 2;
    const uint8_t* A1 = PROJ ? Al + (size_t)z * strideAz * 2 : nullptr;
    const uint8_t* B0 = Bh + (size_t)(z >> bShift) * strideBz * 2;
    const uint8_t* B1 = PROJ ? Bl + (size_t)(z >> bShift) * strideBz * 2 : nullptr;

    const int nch = K >> 5;   // Kc = 32

#define LOAD_TILE(srcB, ldE, rowB, k0, dstOff)                                        \
    { _Pragma("unroll") for (int p_ = 0; p_ < 2; ++p_) {                              \
        int idx_ = tid + 256 * p_;                                                    \
        int row_ = idx_ >> 2, c_ = idx_ & 3;                                          \
        const uint8_t* g_ = (srcB) +                                                  \
            ((size_t)((rowB) + row_) * (ldE) + (k0) + c_ * 8) * 2;                    \
        uint32_t d_ = sb + (dstOff) + row_ * 64 + ((c_ ^ ((row_ >> 1) & 3)) << 4);    \
        CP16(d_, g_); } }

#define LOAD_CHUNK(i_, s_)                                                            \
    {                                                                                 \
        const int k0_ = (i_) * 32;                                                    \
        const int so_ = (s_) * STAGE;                                                 \
        if (PROJ) {                                                                   \
            LOAD_TILE(A0, lda, mBase, k0_, so_);                                      \
            LOAD_TILE(A1, lda, mBase, k0_, so_ + 8192);                               \
            LOAD_TILE(B0, ldb, nBase, k0_, so_ + 16384);                              \
            LOAD_TILE(B1, ldb, nBase, k0_, so_ + 24576);                              \
        } else {                                                                      \
            LOAD_TILE(A0, lda, mBase, k0_, so_);                                      \
            LOAD_TILE(B0, ldb, nBase, k0_, so_ + 8192);                               \
        }                                                                             \
        CP_COMMIT();                                                                  \
    }

    // ldmatrix geometry (64B rows)
    const int lrow  = (lane & 7) + ((lane >> 3) & 1) * 8;
    const int khalf = (lane >> 4) & 1;
    const int swz4  = (lrow >> 1) & 3;
    int rA[4], rB[2];
#pragma unroll
    for (int bm = 0; bm < 4; ++bm) rA[bm] = (wm * 64 + bm * 16 + lrow) * 64;
#pragma unroll
    for (int nb = 0; nb < 2; ++nb) rB[nb] = (wn * 32 + nb * 16 + lrow) * 64;

    float acc[4][4][4];
#pragma unroll
    for (int a = 0; a < 4; ++a)
#pragma unroll
        for (int b = 0; b < 4; ++b)
#pragma unroll
            for (int c = 0; c < 4; ++c) acc[a][b][c] = 0.f;

    // prologue: NSTAGE-1 chunks in flight
#pragma unroll
    for (int p = 0; p < NSTAGE - 1; ++p)
        if (p < nch) LOAD_CHUNK(p, p);

    int st = 0;
    for (int i = 0; i < nch; ++i) {
        const int rem = nch - 1 - i;    // chunks remaining after this one
        if (NSTAGE == 4) {
            if (rem >= 2)      { CP_WAIT2(); }
            else if (rem == 1) { CP_WAIT1(); }
            else               { CP_WAIT0(); }
        } else {
            if (rem >= 1)      { CP_WAIT1(); }
            else               { CP_WAIT0(); }
        }
        __syncthreads();
        if (i + NSTAGE - 1 < nch) {
            int s2 = st + NSTAGE - 1; if (s2 >= NSTAGE) s2 -= NSTAGE;
            LOAD_CHUNK(i + NSTAGE - 1, s2);
        }

        const uint32_t so = sb + st * STAGE;
        const uint32_t sA  = so;
        const uint32_t sAl = so + 8192;                    // PROJ only
        const uint32_t sBh = so + (PROJ ? 16384 : 8192);
        const uint32_t sBl = so + 24576;                   // PROJ only

#pragma unroll
        for (int ks = 0; ks < 2; ++ks) {
            const int cb = (((ks * 2 + khalf) ^ swz4) << 4);
            uint32_t ah[4][4];
#pragma unroll
            for (int bm = 0; bm < 4; ++bm)
                LDSM4(ah[bm][0], ah[bm][1], ah[bm][2], ah[bm][3], sA + rA[bm] + cb);
            uint32_t bh[4][2];
#pragma unroll
            for (int nb = 0; nb < 2; ++nb) {
                uint32_t t0, t1, t2, t3;
                LDSM4(t0, t1, t2, t3, sBh + rB[nb] + cb);
                bh[nb * 2][0] = t0; bh[nb * 2][1] = t2;
                bh[nb * 2 + 1][0] = t1; bh[nb * 2 + 1][1] = t3;
            }
            if (!PROJ) {
#pragma unroll
                for (int bm = 0; bm < 4; ++bm)
#pragma unroll
                    for (int bn = 0; bn < 4; ++bn) MMA_FP16(acc[bm][bn], ah[bm], bh[bn]);
            } else {
#pragma unroll
                for (int bm = 0; bm < 4; ++bm)
#pragma unroll
                    for (int bn = 0; bn < 4; ++bn) MMA_BF16(acc[bm][bn], ah[bm], bh[bn]);
                {
                    uint32_t al[4][4];
#pragma unroll
                    for (int bm = 0; bm < 4; ++bm)
                        LDSM4(al[bm][0], al[bm][1], al[bm][2], al[bm][3], sAl + rA[bm] + cb);
#pragma unroll
                    for (int bm = 0; bm < 4; ++bm)
#pragma unroll
                        for (int bn = 0; bn < 4; ++bn) MMA_BF16(acc[bm][bn], al[bm], bh[bn]);
                }
                {
                    uint32_t bl[4][2];
#pragma unroll
                    for (int nb = 0; nb < 2; ++nb) {
                        uint32_t t0, t1, t2, t3;
                        LDSM4(t0, t1, t2, t3, sBl + rB[nb] + cb);
                        bl[nb * 2][0] = t0; bl[nb * 2][1] = t2;
                        bl[nb * 2 + 1][0] = t1; bl[nb * 2 + 1][1] = t3;
                    }
#pragma unroll
                    for (int bm = 0; bm < 4; ++bm)
#pragma unroll
                        for (int bn = 0; bn < 4; ++bn) MMA_BF16(acc[bm][bn], ah[bm], bl[bn]);
                }
            }
        }
        if (++st == NSTAGE) st = 0;
        if (i + 1 < nch) __syncthreads();
    }
#undef LOAD_CHUNK
#undef LOAD_TILE

    // ======================= epilogue =======================
    const int g4 = lane >> 2, t4 = lane & 3;
#pragma unroll
    for (int bm = 0; bm < 4; ++bm) {
#pragma unroll
        for (int bn = 0; bn < 4; ++bn) {
            const int r0 = mBase + wm * 64 + bm * 16 + g4;
            const int c0 = nBase + wn * 32 + bn * 8 + t4 * 2;
            const float* a4 = acc[bm][bn];
#pragma unroll
            for (int half = 0; half < 2; ++half) {
                const int gr = r0 + half * 8;
                const float v0 = a4[half * 2 + 0];
                const float v1 = a4[half * 2 + 1];
                if (MODE == 1) {
                    float2 q; q.x = v0 * 0.0625f; q.y = v1 * 0.0625f;
                    *reinterpret_cast<float2*>(
                        ep_f + (size_t)z * strideEz + (size_t)gr * SEQ + c0) = q;
                } else if (MODE == 3) {
                    size_t off = (size_t)gr * DIM + c0;
                    float2 rx = *reinterpret_cast<const float2*>(resid + off);
                    float2 q; q.x = v0 + rx.x; q.y = v1 + rx.y;
                    *reinterpret_cast<float2*>(ep_f + off) = q;
                } else if (MODE == 4) {
                    const int bb = gr >> 11, rr = gr & 2047;
                    const int hh = rr >> 9, ib = (rr & 511) << 2;
                    const int ii = ib | (c0 >> 8), dd = c0 & 255;
                    size_t base = (size_t)z * strideEz +
                                  ((size_t)(bb * 4 + hh) * SEQ + ii) * DIM + dd;
                    *reinterpret_cast<__half2*>((__half*)ep_a + base) =
                        __floats2half2_rn(v0, v1);
                } else {  // MODE 2: fp16 single att
                    const int bb = z >> 2, h = z & 3;
                    size_t base = ((size_t)(bb * SEQ + gr)) * HD + h * DIM + c0;
                    *reinterpret_cast<__half2*>((__half*)ep_a + base) =
                        __floats2half2_rn(v0, v1);
                }
            }
        }
    }
}

// ======================= softmax (fp32 in-place + fp16 copy) =======================
__global__ void k_softmax(float* __restrict__ probs, __half* __restrict__ pf)
{
    const size_t row = blockIdx.x;
    float4* p4 = reinterpret_cast<float4*>(probs + row * SEQ);
    const int t = threadIdx.x;
    const int wid = t >> 5, lane = t & 31;
    __shared__ float red[8];

    float4 v[2];
    v[0] = p4[t]; v[1] = p4[t + 256];
    float mx = fmaxf(fmaxf(fmaxf(v[0].x, v[0].y), fmaxf(v[0].z, v[0].w)),
                     fmaxf(fmaxf(v[1].x, v[1].y), fmaxf(v[1].z, v[1].w)));
#pragma unroll
    for (int s = 16; s > 0; s >>= 1) mx = fmaxf(mx, __shfl_xor_sync(~0u, mx, s));
    if (lane == 0) red[wid] = mx;
    __syncthreads();
    float m0 = red[lane & 7];
#pragma unroll
    for (int s = 4; s > 0; s >>= 1) m0 = fmaxf(m0, __shfl_xor_sync(~0u, m0, s));
    mx = __shfl_sync(~0u, m0, 0);

    float sum = 0.f;
#pragma unroll
    for (int q = 0; q < 2; ++q) {
        v[q].x = __expf(v[q].x - mx); v[q].y = __expf(v[q].y - mx);
        v[q].z = __expf(v[q].z - mx); v[q].w = __expf(v[q].w - mx);
        sum += v[q].x + v[q].y + v[q].z + v[q].w;
    }
#pragma unroll
    for (int s = 16; s > 0; s >>= 1) sum += __shfl_xor_sync(~0u, sum, s);
    __syncthreads();
    if (lane == 0) red[wid] = sum;
    __syncthreads();
    float s0 = red[lane & 7];
#pragma unroll
    for (int s = 4; s > 0; s >>= 1) s0 += __shfl_xor_sync(~0u, s0, s);
    const float inv = 1.0f / __shfl_sync(~0u, s0, 0);

#pragma unroll
    for (int q = 0; q < 2; ++q) {
        v[q].x *= inv; v[q].y *= inv; v[q].z *= inv; v[q].w *= inv;
    }
    p4[t] = v[0]; p4[t + 256] = v[1];

    __half2* pf2 = reinterpret_cast<__half2*>(pf + row * SEQ);
    pf2[2 * t]             = __floats2half2_rn(v[0].x, v[0].y);
    pf2[2 * t + 1]         = __floats2half2_rn(v[0].z, v[0].w);
    pf2[2 * (t + 256)]     = __floats2half2_rn(v[1].x, v[1].y);
    pf2[2 * (t + 256) + 1] = __floats2half2_rn(v[1].z, v[1].w);
}

// ======================= LayerNorm =======================
__global__ void k_ln(const float* __restrict__ Z, const float* __restrict__ gamma,
                     const float* __restrict__ beta, float* __restrict__ outp)
{
    const int R = blockIdx.x;
    const int t = threadIdx.x;
    __shared__ float red[256];

    float zv = Z[(size_t)R * DIM + t];
    red[t] = zv; __syncthreads();
    for (int s = 128; s > 0; s >>= 1) {
        if (t < s) red[t] += red[t + s];
        __syncthreads();
    }
    float mu = red[0] * (1.0f / 256.0f);
    __syncthreads();
    float dev = zv - mu;
    red[t] = dev * dev; __syncthreads();
    for (int s = 128; s > 0; s >>= 1) {
        if (t < s) red[t] += red[t + s];
        __syncthreads();
    }
    float var = red[0] * (1.0f / 256.0f);
    outp[(size_t)R * DIM + t] = dev * rsqrtf(var + 1e-5f) * gamma[t] + beta[t];
}

// ======================= launch =======================
extern "C" void kernel_launch(void* const* d_in, const int* in_sizes, int n_in,
                              void* d_out, int out_size)
{
    const float* x     = (const float*)d_in[0];
    const float* Wq    = (const float*)d_in[1];
    const float* Wk    = (const float*)d_in[2];
    const float* Wv    = (const float*)d_in[3];
    const float* gamma = (const float*)d_in[4];
    const float* beta  = (const float*)d_in[5];

    bf16 *xh, *xl, *wqkth, *wqktl;
    __half *xTf, *wvtf, *QKf, *Pf, *attf;
    float *Z, *outFb, *probsFb;
    cudaGetSymbolAddress((void**)&xh, g_xh);       cudaGetSymbolAddress((void**)&xl, g_xl);
    cudaGetSymbolAddress((void**)&xTf, g_xTf);
    cudaGetSymbolAddress((void**)&wqkth, g_wqkth); cudaGetSymbolAddress((void**)&wqktl, g_wqktl);
    cudaGetSymbolAddress((void**)&wvtf, g_wvtf);
    cudaGetSymbolAddress((void**)&QKf, g_QKf);
    cudaGetSymbolAddress((void**)&Pf, g_Pf);
    cudaGetSymbolAddress((void**)&attf, g_attf);
    cudaGetSymbolAddress((void**)&Z, g_Z);
    cudaGetSymbolAddress((void**)&outFb, g_out_fb);
    cudaGetSymbolAddress((void**)&probsFb, g_probs_fb);

    const long long OUT_E = (long long)BS * SEQ * DIM;
    const long long PR_E  = (long long)BHN * SEQ * SEQ;
    long long osz = out_size;
    float *outp, *probs;
    if (osz >= OUT_E + PR_E) { outp = (float*)d_out; probs = (float*)d_out + OUT_E; }
    else if (osz >= PR_E)    { probs = (float*)d_out; outp = outFb; }
    else                     { outp = (float*)d_out; probs = probsFb; }

    cudaFuncSetAttribute(k_mma<4>, cudaFuncAttributeMaxDynamicSharedMemorySize, 98304);
    cudaFuncSetAttribute(k_mma<1>, cudaFuncAttributeMaxDynamicSharedMemorySize, 65536);
    cudaFuncSetAttribute(k_mma<2>, cudaFuncAttributeMaxDynamicSharedMemorySize, 65536);
    cudaFuncSetAttribute(k_mma<3>, cudaFuncAttributeMaxDynamicSharedMemorySize, 65536);

    dim3 T(256);
    const size_t QK_Z = (size_t)BHN * SEQ * DIM;   // elements per projection output

    // 1: fused prep
    k_prep<<<3840, T>>>(x, Wq, Wk, Wv, xh, xl, xTf, wqkth, wqktl, wvtf);

    // 2: Q+K projections merged (z=0 -> Qf, z=1 -> Kf), bf16 3-product
    k_mma<4><<<dim3(8, 64, 2), T, 98304>>>((const uint8_t*)xh, (const uint8_t*)xl,
        (const uint8_t*)wqkth, (const uint8_t*)wqktl, 256, 256, 256,
        0, (size_t)HD * DIM, 0, nullptr, QKf, nullptr, QK_Z);

    // 3: scores (per bh: 2048x2048, K=256), fp16 1-product, 4-stage
    k_mma<1><<<dim3(16, 16, BHN), T, 65536>>>((const uint8_t*)QKf, nullptr,
        (const uint8_t*)(QKf + QK_Z), nullptr, 256, 256, 256,
        (size_t)SEQ * DIM, (size_t)SEQ * DIM, 0,
        probs, nullptr, nullptr, (size_t)SEQ * SEQ);

    // 4: softmax (fp32 + fp16 copy)
    k_softmax<<<BHN * SEQ, T>>>(probs, Pf);

    // 5: PV (per bh: 2048x256, K=2048), fp16 1-product, 4-stage
    k_mma<2><<<dim3(2, 16, BHN), T, 65536>>>((const uint8_t*)Pf, nullptr,
        (const uint8_t*)xTf, nullptr, 2048, 2048, 2048,
        (size_t)SEQ * SEQ, (size_t)DIM * SEQ, 2,
        nullptr, attf, nullptr, 0);

    // 6: att @ Wv + x (M=8192, N=256, K=1024), fp16 1-product, 4-stage
    k_mma<3><<<dim3(2, 64, 1), T, 65536>>>((const uint8_t*)attf, nullptr,
        (const uint8_t*)wvtf, nullptr, 1024, 1024, 1024,
        0, 0, 0, Z, nullptr, x, 0);

    // 7: LayerNorm
    k_ln<<<BS * SEQ, T>>>(Z, gamma, beta, outp);
}